// round 9
// baseline (speedup 1.0000x reference)
#include <cuda_runtime.h>
#include <cuda_bf16.h>
#include <math.h>
#include <stdint.h>

// Problem constants
#define BB 4
#define TT 2048
#define CC 1024
#define HH 16
#define HD 64
#define MROWS (BB * TT)          // 8192
#define N_QKV (3 * CC)           // 3072

// ---------------------------------------------------------------------------
// Global scratch (bf16 hi/lo pairs everywhere; allocation-free)
// ---------------------------------------------------------------------------
__device__ __nv_bfloat16 g_xh[MROWS * CC],  g_xl[MROWS * CC];
__device__ __nv_bfloat16 g_wqh[N_QKV * CC], g_wql[N_QKV * CC];
__device__ __nv_bfloat16 g_wph[CC * CC],    g_wpl[CC * CC];
__device__ __nv_bfloat16 g_qh[BB * HH * TT * HD], g_ql[BB * HH * TT * HD]; // [bh][t][d]
__device__ __nv_bfloat16 g_kh[BB * HH * TT * HD], g_kl[BB * HH * TT * HD]; // [bh][t][d]
__device__ __nv_bfloat16 g_vh[BB * HH * TT * HD], g_vl[BB * HH * TT * HD]; // [bh][d][t]
__device__ __nv_bfloat16 g_ah[MROWS * CC],  g_al[MROWS * CC];              // att out [B,T,C]

// ---------------------------------------------------------------------------
// Helpers
// ---------------------------------------------------------------------------
__device__ __forceinline__ uint32_t b2u(__nv_bfloat162 h) {
    return *reinterpret_cast<uint32_t*>(&h);
}
__device__ __forceinline__ uint32_t smem_u32(const void* p) {
    uint32_t a;
    asm("{ .reg .u64 t; cvta.to.shared.u64 t, %1; cvt.u32.u64 %0, t; }"
        : "=r"(a) : "l"(p));
    return a;
}
__device__ __forceinline__ void cpa16(uint32_t dst, const void* src) {
    asm volatile("cp.async.cg.shared.global [%0], [%1], 16;"
                 :: "r"(dst), "l"(src) : "memory");
}
#define CP_COMMIT() asm volatile("cp.async.commit_group;" ::: "memory")
#define CP_WAIT0()  asm volatile("cp.async.wait_group 0;" ::: "memory")
#define CP_WAIT1()  asm volatile("cp.async.wait_group 1;" ::: "memory")

#define LDSM4(r, addr) \
    asm volatile("ldmatrix.sync.aligned.m8n8.x4.shared.b16 {%0,%1,%2,%3}, [%4];" \
        : "=r"((r)[0]), "=r"((r)[1]), "=r"((r)[2]), "=r"((r)[3]) : "r"(addr))

__device__ __forceinline__ void mma16816(float* c, const uint32_t* a,
                                         uint32_t b0, uint32_t b1) {
    asm volatile(
        "mma.sync.aligned.m16n8k16.row.col.f32.bf16.bf16.f32 "
        "{%0,%1,%2,%3}, {%4,%5,%6,%7}, {%8,%9}, {%0,%1,%2,%3};"
        : "+f"(c[0]), "+f"(c[1]), "+f"(c[2]), "+f"(c[3])
        : "r"(a[0]), "r"(a[1]), "r"(a[2]), "r"(a[3]), "r"(b0), "r"(b1));
}

// ---------------------------------------------------------------------------
// Elementwise fp32 -> bf16 hi/lo split
// ---------------------------------------------------------------------------
__global__ void split_kernel(const float* __restrict__ src,
                             __nv_bfloat16* __restrict__ dh,
                             __nv_bfloat16* __restrict__ dl, int n4) {
    int i = blockIdx.x * blockDim.x + threadIdx.x;
    int stride = gridDim.x * blockDim.x;
    for (; i < n4; i += stride) {
        float4 v = ((const float4*)src)[i];
        __nv_bfloat162 h01 = __floats2bfloat162_rn(v.x, v.y);
        __nv_bfloat162 h23 = __floats2bfloat162_rn(v.z, v.w);
        __nv_bfloat162 l01 = __floats2bfloat162_rn(v.x - __bfloat162float(h01.x),
                                                   v.y - __bfloat162float(h01.y));
        __nv_bfloat162 l23 = __floats2bfloat162_rn(v.z - __bfloat162float(h23.x),
                                                   v.w - __bfloat162float(h23.y));
        ((uint2*)dh)[i] = make_uint2(b2u(h01), b2u(h23));
        ((uint2*)dl)[i] = make_uint2(b2u(l01), b2u(l23));
    }
}

// ---------------------------------------------------------------------------
// Split-bf16 NT GEMM, 3-stage cp.async pipeline, swizzled 64B rows,
// ldmatrix fragments, 2 CTAs/SM, ONE barrier per chunk.
// C[m,n] = sum_k A[m,k]*B[n,k]. 128x128 tile, K-chunk 32, 8 warps 4x2.
// Swizzle: 16B-unit column c (0..3) stored at c ^ ((row>>1)&3).
// EPI=0: write Q/K/V split bf16 (V transposed). EPI=1: out = C + bias (fp32).
// ---------------------------------------------------------------------------
#define TILE_B 8192                        // 128 rows x 64B (no pad, swizzled)
#define BUF_B  (4 * TILE_B)                // AH, AL, BH, BL = 32768
#define NSTAGE 3
#define GEMM_SMEM (NSTAGE * BUF_B)         // 98304 (also covers Ds 128x132 f32)
#define NCHUNK (CC / 32)                   // 32

template <int EPI>
__global__ __launch_bounds__(256, 2) void tc_gemm(
    const __nv_bfloat16* __restrict__ AH, const __nv_bfloat16* __restrict__ AL,
    const __nv_bfloat16* __restrict__ BH, const __nv_bfloat16* __restrict__ BL,
    const float* __restrict__ bias, float* __restrict__ out) {
    extern __shared__ __align__(1024) char smc[];
    const uint32_t smb = smem_u32(smc);
    const int tid = threadIdx.x;
    const int m0 = blockIdx.y * 128;
    const int n0 = blockIdx.x * 128;
    const int wid = tid >> 5;
    const int lane = tid & 31;
    const int gid = lane >> 2;
    const int tig = lane & 3;
    const int wm = wid & 3;
    const int wn = wid >> 2;

    // ldmatrix lane offsets (swizzled); '^ (ks<<5)' selects the K-step.
    // A: m0=(r0-7,k0-7) m1=(r8-15,k0-7) m2=(r0-7,k8-15) m3=(r8-15,k8-15)
    {
    }
    const int rowA = (lane & 7) + ((lane >> 3) & 1) * 8;
    const int hiA  = lane >> 4;
    const uint32_t laneA0 = (uint32_t)(rowA * 64 + ((hiA ^ ((rowA >> 1) & 3)) << 4));
    // B: m0=(n0-7,k0-7) m1=(n0-7,k8-15) m2=(n8-15,k0-7) m3=(n8-15,k8-15)
    const int rowB = (lane & 7) + ((lane >> 4) & 1) * 8;
    const int hiB  = (lane >> 3) & 1;
    const uint32_t laneB0 = (uint32_t)(rowB * 64 + ((hiB ^ ((rowB >> 1) & 3)) << 4));

    float acc[2][8][4];
#pragma unroll
    for (int i = 0; i < 2; i++)
#pragma unroll
        for (int j = 0; j < 8; j++)
#pragma unroll
            for (int q = 0; q < 4; q++) acc[i][j][q] = 0.f;

    // cp.async one chunk (4 tiles x 512 x 16B) into stage bufi
    auto copyc = [&](int kk, int bufi) {
        uint32_t bbase = smb + bufi * BUF_B;
#pragma unroll
        for (int l = 0; l < 8; l++) {
            const int tile = l >> 1;                 // compile-time per unroll
            int e2 = (l & 1) * 256 + tid;            // 0..511
            int r = e2 >> 2;                         // row 0..127
            int q = e2 & 3;                          // 16B col 0..3
            const __nv_bfloat16* src =
                (tile == 0) ? AH : (tile == 1) ? AL : (tile == 2) ? BH : BL;
            int row = (tile < 2 ? m0 : n0) + r;
            cpa16(bbase + tile * TILE_B + r * 64 + ((q ^ ((r >> 1) & 3)) << 4),
                  src + (size_t)row * CC + kk + q * 8);
        }
    };

    auto compute = [&](uint32_t bufu) {
#pragma unroll
        for (int ks = 0; ks < 2; ks++) {
            uint32_t ah[2][4], al[2][4];
#pragma unroll
            for (int i = 0; i < 2; i++) {
                uint32_t aaddr = (bufu + (wm * 32 + i * 16) * 64) ^ (laneA0 ^ (ks << 5));
                // (XOR-combining is safe: operands occupy disjoint bit ranges)
                aaddr = bufu + (wm * 32 + i * 16) * 64 + (laneA0 ^ (ks << 5));
                LDSM4(ah[i], aaddr);
                LDSM4(al[i], aaddr + TILE_B);
            }
#pragma unroll
            for (int jp = 0; jp < 4; jp++) {
                uint32_t baddr = bufu + 2 * TILE_B + (wn * 64 + jp * 16) * 64
                               + (laneB0 ^ (ks << 5));
                uint32_t rh[4], rl[4];
                LDSM4(rh, baddr);
                LDSM4(rl, baddr + TILE_B);
#pragma unroll
                for (int t = 0; t < 2; t++) {
                    int j = 2 * jp + t;
#pragma unroll
                    for (int i = 0; i < 2; i++) {
                        mma16816(acc[i][j], ah[i], rh[2 * t], rh[2 * t + 1]);
                        mma16816(acc[i][j], ah[i], rl[2 * t], rl[2 * t + 1]);
                        mma16816(acc[i][j], al[i], rh[2 * t], rh[2 * t + 1]);
                    }
                }
            }
        }
    };

    // 3-stage pipeline, one barrier per chunk:
    //   wait(chunk c ready) -> bar -> prefetch(c+2) -> compute(c)
    copyc(0, 0);  CP_COMMIT();
    copyc(32, 1); CP_COMMIT();
    for (int c = 0; c < NCHUNK; c++) {
        if (c + 1 < NCHUNK) { CP_WAIT1(); } else { CP_WAIT0(); }
        __syncthreads();                    // all done with buffer (c+2)%3's old data
        if (c + 2 < NCHUNK) {
            copyc((c + 2) * 32, (c + 2) % 3);
            CP_COMMIT();
        }
        compute(smb + (uint32_t)(c % 3) * BUF_B);
    }
    __syncthreads();

    // ---- epilogue: fragments -> smem staging
    float* Ds = (float*)smc;               // 128 x 132 f32 = 67584 <= 98304
#pragma unroll
    for (int i = 0; i < 2; i++) {
        int rr = wm * 32 + i * 16 + gid;
#pragma unroll
        for (int j = 0; j < 8; j++) {
            int cc = wn * 64 + j * 8 + tig * 2;
            *(float2*)&Ds[rr * 132 + cc]       = make_float2(acc[i][j][0], acc[i][j][1]);
            *(float2*)&Ds[(rr + 8) * 132 + cc] = make_float2(acc[i][j][2], acc[i][j][3]);
        }
    }
    __syncthreads();

    if (EPI == 1) {
#pragma unroll 4
        for (int ll = 0; ll < 64; ll++) {
            int flat = ll * 256 + tid;
            int n = flat & 127;
            int m = flat >> 7;
            out[(size_t)(m0 + m) * CC + n0 + n] = Ds[m * 132 + n] + bias[n0 + n];
        }
    } else {
        // two 64-wide segments; each wholly one of q/k/v (192 % 64 == 0)
#pragma unroll
        for (int seg = 0; seg < 2; seg++) {
            int gn0 = n0 + seg * 64;
            int h = gn0 / 192;
            int part = (gn0 % 192) >> 6;
            if (part < 2) {
                __nv_bfloat16* dh = (part == 0) ? g_qh : g_kh;
                __nv_bfloat16* dl = (part == 0) ? g_ql : g_kl;
#pragma unroll
                for (int it = 0; it < 16; it++) {
                    int m = it * 8 + (tid >> 5);
                    int d2 = (tid & 31) * 2;
                    float v0 = Ds[m * 132 + seg * 64 + d2];
                    float v1 = Ds[m * 132 + seg * 64 + d2 + 1];
                    __nv_bfloat162 hp = __floats2bfloat162_rn(v0, v1);
                    __nv_bfloat162 lp = __floats2bfloat162_rn(
                        v0 - __bfloat162float(hp.x), v1 - __bfloat162float(hp.y));
                    int gm = m0 + m; int b = gm >> 11; int t = gm & 2047;
                    size_t idx = (((size_t)(b * HH + h)) * TT + t) * HD + d2;
                    *(__nv_bfloat162*)(dh + idx) = hp;
                    *(__nv_bfloat162*)(dl + idx) = lp;
                }
            } else {                        // V: transposed [bh][d][t]
#pragma unroll
                for (int it = 0; it < 16; it++) {
                    int flat = it * 256 + tid;     // 0..4095
                    int d = flat >> 6;             // 0..63
                    int tp = (flat & 63) * 2;      // 0..126 (pair along t)
                    float v0 = Ds[tp * 132 + seg * 64 + d];
                    float v1 = Ds[(tp + 1) * 132 + seg * 64 + d];
                    __nv_bfloat162 hp = __floats2bfloat162_rn(v0, v1);
                    __nv_bfloat162 lp = __floats2bfloat162_rn(
                        v0 - __bfloat162float(hp.x), v1 - __bfloat162float(hp.y));
                    int gm = m0 + tp; int b = gm >> 11; int t = gm & 2047;
                    size_t idx = (((size_t)(b * HH + h)) * HD + d) * TT + t;
                    *(__nv_bfloat162*)(g_vh + idx) = hp;
                    *(__nv_bfloat162*)(g_vl + idx) = lp;
                }
            }
        }
    }
}

// ---------------------------------------------------------------------------
// Flash attention (unchanged from R7). split-bf16 mma + ldmatrix.
// BM=128 (8 warps x 16 rows), BN=64. cp.async double-buffered K/V tiles.
// Smem row stride 144B (16B-mult, LDSM conflict-free).
// ---------------------------------------------------------------------------
#define AT_ROW 144
#define AT_TILE (64 * AT_ROW)              // 9216
#define AT_BUF (4 * AT_TILE)               // 36864
#define ATT_SMEM_BYTES (2 * AT_BUF)        // 73728

__global__ __launch_bounds__(256) void attn_kernel() {
    extern __shared__ __align__(1024) char smc[];
    const uint32_t smb = smem_u32(smc);
    const int tid = threadIdx.x;
    const int bh = blockIdx.y;
    const int q0 = blockIdx.x * 128;
    const int wid = tid >> 5;
    const int lane = tid & 31;
    const int gid = lane >> 2;
    const int tig = lane & 3;
    const int r0 = q0 + wid * 16 + gid;

    const __nv_bfloat16* Qh = g_qh + (size_t)bh * TT * HD;
    const __nv_bfloat16* Ql = g_ql + (size_t)bh * TT * HD;
    const __nv_bfloat16* Kh = g_kh + (size_t)bh * TT * HD;
    const __nv_bfloat16* Kl = g_kl + (size_t)bh * TT * HD;
    const __nv_bfloat16* Vh = g_vh + (size_t)bh * HD * TT;
    const __nv_bfloat16* Vl = g_vl + (size_t)bh * HD * TT;

    // B-operand ldmatrix lane offset (stride AT_ROW)
    const uint32_t laneB = (uint32_t)(((lane & 7) + ((lane >> 4) & 1) * 8) * AT_ROW
                                      + ((lane >> 3) & 1) * 16);

    // ---- Q fragments (pre-split), direct ldg
    uint32_t qh[4][4], ql[4][4];
#pragma unroll
    for (int ks = 0; ks < 4; ks++)
#pragma unroll
        for (int hv = 0; hv < 2; hv++)
#pragma unroll
            for (int rr = 0; rr < 2; rr++) {
                size_t o = (size_t)(r0 + rr * 8) * HD + ks * 16 + hv * 8 + tig * 2;
                qh[ks][hv * 2 + rr] = *(const uint32_t*)(Qh + o);
                ql[ks][hv * 2 + rr] = *(const uint32_t*)(Ql + o);
            }

    float oacc[8][4];
#pragma unroll
    for (int j = 0; j < 8; j++)
#pragma unroll
        for (int q = 0; q < 4; q++) oacc[j][q] = 0.f;
    float mr0 = -1e30f, mr1 = -1e30f, lr0 = 0.f, lr1 = 0.f;

    auto copyc = [&](int c, int bufi) {
        const int k0 = c * 64;
        uint32_t bbase = smb + bufi * AT_BUF;
#pragma unroll
        for (int l = 0; l < 8; l++) {
            const int tile = l >> 1;
            int e2 = (l & 1) * 256 + tid;       // 0..511
            int r = e2 >> 3;                    // 0..63
            int q = e2 & 7;                     // 0..7
            const __nv_bfloat16* src;
            if (tile == 0)      src = Kh + (size_t)(k0 + r) * HD + q * 8;
            else if (tile == 1) src = Kl + (size_t)(k0 + r) * HD + q * 8;
            else if (tile == 2) src = Vh + (size_t)r * TT + k0 + q * 8;
            else                src = Vl + (size_t)r * TT + k0 + q * 8;
            cpa16(bbase + tile * AT_TILE + r * AT_ROW + q * 16, src);
        }
    };

    const int jmax = (q0 >> 6) + 2;
    copyc(0, 0);
    CP_COMMIT();
    for (int c = 0; c < jmax; c++) {
        if (c + 1 < jmax) {
            copyc(c + 1, (c + 1) & 1);
            CP_COMMIT();
            CP_WAIT1();
        } else {
            CP_WAIT0();
        }
        __syncthreads();
        const uint32_t KT = smb + (uint32_t)(c & 1) * AT_BUF;
        const uint32_t VT = KT + 2 * AT_TILE;

        // ---- S = Q K^T (qh*kh + qh*kl + ql*kh)
        float s[8][4];
#pragma unroll
        for (int j = 0; j < 8; j++)
#pragma unroll
            for (int q = 0; q < 4; q++) s[j][q] = 0.f;
#pragma unroll
        for (int ks = 0; ks < 4; ks++) {
#pragma unroll
            for (int jp = 0; jp < 4; jp++) {
                uint32_t kaddr = KT + laneB + jp * 16 * AT_ROW + ks * 32;
                uint32_t rh[4], rl[4];
                LDSM4(rh, kaddr);
                LDSM4(rl, kaddr + AT_TILE);
#pragma unroll
                for (int t = 0; t < 2; t++) {
                    int j = 2 * jp + t;
                    mma16816(s[j], qh[ks], rh[2 * t], rh[2 * t + 1]);
                    mma16816(s[j], qh[ks], rl[2 * t], rl[2 * t + 1]);
                    mma16816(s[j], ql[ks], rh[2 * t], rh[2 * t + 1]);
                }
            }
        }

        const int k0 = c * 64;
#pragma unroll
        for (int j = 0; j < 8; j++)
#pragma unroll
            for (int q = 0; q < 4; q++) s[j][q] *= 0.125f;
        if (c >= jmax - 2) {
#pragma unroll
            for (int j = 0; j < 8; j++) {
                int col = k0 + 8 * j + 2 * tig;
                if (col > r0)          s[j][0] = -1e30f;
                if (col + 1 > r0)      s[j][1] = -1e30f;
                if (col > r0 + 8)      s[j][2] = -1e30f;
                if (col + 1 > r0 + 8)  s[j][3] = -1e30f;
            }
        }

        // ---- online softmax
        float pm0 = -1e30f, pm1 = -1e30f;
#pragma unroll
        for (int j = 0; j < 8; j++) {
            pm0 = fmaxf(pm0, fmaxf(s[j][0], s[j][1]));
            pm1 = fmaxf(pm1, fmaxf(s[j][2], s[j][3]));
        }
        pm0 = fmaxf(pm0, __shfl_xor_sync(0xffffffffu, pm0, 1));
        pm0 = fmaxf(pm0, __shfl_xor_sync(0xffffffffu, pm0, 2));
        pm1 = fmaxf(pm1, __shfl_xor_sync(0xffffffffu, pm1, 1));
        pm1 = fmaxf(pm1, __shfl_xor_sync(0xffffffffu, pm1, 2));
        float mn0 = fmaxf(mr0, pm0), mn1 = fmaxf(mr1, pm1);
        float a0 = __expf(mr0 - mn0), a1 = __expf(mr1 - mn1);
        float sum0 = 0.f, sum1 = 0.f;
#pragma unroll
        for (int j = 0; j < 8; j++) {
            s[j][0] = __expf(s[j][0] - mn0);
            s[j][1] = __expf(s[j][1] - mn0);
            s[j][2] = __expf(s[j][2] - mn1);
            s[j][3] = __expf(s[j][3] - mn1);
            sum0 += s[j][0] + s[j][1];
            sum1 += s[j][2] + s[j][3];
        }
        sum0 += __shfl_xor_sync(0xffffffffu, sum0, 1);
        sum0 += __shfl_xor_sync(0xffffffffu, sum0, 2);
        sum1 += __shfl_xor_sync(0xffffffffu, sum1, 1);
        sum1 += __shfl_xor_sync(0xffffffffu, sum1, 2);
        lr0 = lr0 * a0 + sum0;
        lr1 = lr1 * a1 + sum1;
        mr0 = mn0; mr1 = mn1;
#pragma unroll
        for (int j = 0; j < 8; j++) {
            oacc[j][0] *= a0; oacc[j][1] *= a0;
            oacc[j][2] *= a1; oacc[j][3] *= a1;
        }

        // ---- pack P fragments (bf16 hi/lo) from S accumulators
        uint32_t pah[4][4], pal[4][4];
#pragma unroll
        for (int ks = 0; ks < 4; ks++) {
            int j0 = 2 * ks, j1 = 2 * ks + 1;
#pragma unroll
            for (int part = 0; part < 4; part++) {
                int jj = (part < 2) ? j0 : j1;
                int qa = (part & 1) * 2;
                float x = s[jj][qa], y = s[jj][qa + 1];
                __nv_bfloat162 hp = __floats2bfloat162_rn(x, y);
                __nv_bfloat162 lp = __floats2bfloat162_rn(
                    x - __bfloat162float(hp.x), y - __bfloat162float(hp.y));
                pah[ks][part] = b2u(hp);
                pal[ks][part] = b2u(lp);
            }
        }

        // ---- O += P V (ph*vh + ph*vl + pl*vh)
#pragma unroll
        for (int ks = 0; ks < 4; ks++) {
#pragma unroll
            for (int jp = 0; jp < 4; jp++) {
                uint32_t vaddr = VT + laneB + jp * 16 * AT_ROW + ks * 32;
                uint32_t rh[4], rl[4];
                LDSM4(rh, vaddr);
                LDSM4(rl, vaddr + AT_TILE);
#pragma unroll
                for (int t = 0; t < 2; t++) {
                    int j = 2 * jp + t;
                    mma16816(oacc[j], pah[ks], rh[2 * t], rh[2 * t + 1]);
                    mma16816(oacc[j], pah[ks], rl[2 * t], rl[2 * t + 1]);
                    mma16816(oacc[j], pal[ks], rh[2 * t], rh[2 * t + 1]);
                }
            }
        }
        __syncthreads();
    }

    // ---- epilogue: normalize, split bf16, write g_ah/g_al [B,T,C]
    const int b = bh >> 4;
    const int h = bh & 15;
    float inv0 = 1.f / lr0, inv1 = 1.f / lr1;
#pragma unroll
    for (int j = 0; j < 8; j++) {
        int d = 8 * j + 2 * tig;
        size_t o0 = ((size_t)(b * TT + r0)) * CC + h * HD + d;
        size_t o1 = ((size_t)(b * TT + r0 + 8)) * CC + h * HD + d;
        float x0 = oacc[j][0] * inv0, y0 = oacc[j][1] * inv0;
        float x1 = oacc[j][2] * inv1, y1 = oacc[j][3] * inv1;
        __nv_bfloat162 h0 = __floats2bfloat162_rn(x0, y0);
        __nv_bfloat162 l0 = __floats2bfloat162_rn(x0 - __bfloat162float(h0.x),
                                                  y0 - __bfloat162float(h0.y));
        __nv_bfloat162 h1 = __floats2bfloat162_rn(x1, y1);
        __nv_bfloat162 l1 = __floats2bfloat162_rn(x1 - __bfloat162float(h1.x),
                                                  y1 - __bfloat162float(h1.y));
        *(__nv_bfloat162*)(g_ah + o0) = h0;
        *(__nv_bfloat162*)(g_al + o0) = l0;
        *(__nv_bfloat162*)(g_ah + o1) = h1;
        *(__nv_bfloat162*)(g_al + o1) = l1;
    }
}

// ---------------------------------------------------------------------------

extern "C" void kernel_launch(void* const* d_in, const int* in_sizes, int n_in,
                              void* d_out, int out_size) {
    const float* x      = (const float*)d_in[0];
    const float* w_qkv  = (const float*)d_in[1];
    const float* w_proj = (const float*)d_in[2];
    const float* b_proj = (const float*)d_in[3];
    float* out = (float*)d_out;

    __nv_bfloat16 *xh, *xl, *wqh, *wql, *wph, *wpl, *ah, *al;
    cudaGetSymbolAddress((void**)&xh,  g_xh);
    cudaGetSymbolAddress((void**)&xl,  g_xl);
    cudaGetSymbolAddress((void**)&wqh, g_wqh);
    cudaGetSymbolAddress((void**)&wql, g_wql);
    cudaGetSymbolAddress((void**)&wph, g_wph);
    cudaGetSymbolAddress((void**)&wpl, g_wpl);
    cudaGetSymbolAddress((void**)&ah,  g_ah);
    cudaGetSymbolAddress((void**)&al,  g_al);

    cudaFuncSetAttribute(tc_gemm<0>, cudaFuncAttributeMaxDynamicSharedMemorySize, GEMM_SMEM);
    cudaFuncSetAttribute(tc_gemm<1>, cudaFuncAttributeMaxDynamicSharedMemorySize, GEMM_SMEM);
    cudaFuncSetAttribute(attn_kernel, cudaFuncAttributeMaxDynamicSharedMemorySize, ATT_SMEM_BYTES);

    split_kernel<<<2048, 256>>>(x, xh, xl, MROWS * CC / 4);
    split_kernel<<<2048, 256>>>(w_qkv, wqh, wql, N_QKV * CC / 4);
    split_kernel<<<1024, 256>>>(w_proj, wph, wpl, CC * CC / 4);

    tc_gemm<0><<<dim3(N_QKV / 128, MROWS / 128), 256, GEMM_SMEM>>>(
        xh, xl, wqh, wql, nullptr, nullptr);
    attn_kernel<<<dim3(TT / 128, BB * HH), 256, ATT_SMEM_BYTES>>>();
    tc_gemm<1><<<dim3(CC / 128, MROWS / 128), 256, GEMM_SMEM>>>(
        ah, al, wph, wpl, b_proj, out);
}

// round 10
// speedup vs baseline: 1.4773x; 1.4773x over previous
#include <cuda_runtime.h>
#include <cuda_bf16.h>
#include <math.h>
#include <stdint.h>

// Problem constants
#define BB 4
#define TT 2048
#define CC 1024
#define HH 16
#define HD 64
#define MROWS (BB * TT)          // 8192
#define N_QKV (3 * CC)           // 3072

// ---------------------------------------------------------------------------
// Global scratch (bf16 hi/lo pairs everywhere; allocation-free)
// ---------------------------------------------------------------------------
__device__ __nv_bfloat16 g_xh[MROWS * CC],  g_xl[MROWS * CC];
__device__ __nv_bfloat16 g_wqh[N_QKV * CC], g_wql[N_QKV * CC];
__device__ __nv_bfloat16 g_wph[CC * CC],    g_wpl[CC * CC];
__device__ __nv_bfloat16 g_qh[BB * HH * TT * HD], g_ql[BB * HH * TT * HD]; // [bh][t][d]
__device__ __nv_bfloat16 g_kh[BB * HH * TT * HD], g_kl[BB * HH * TT * HD]; // [bh][t][d]
__device__ __nv_bfloat16 g_vh[BB * HH * TT * HD], g_vl[BB * HH * TT * HD]; // [bh][d][t]
__device__ __nv_bfloat16 g_ah[MROWS * CC],  g_al[MROWS * CC];              // att out [B,T,C]

// ---------------------------------------------------------------------------
// Helpers
// ---------------------------------------------------------------------------
__device__ __forceinline__ uint32_t b2u(__nv_bfloat162 h) {
    return *reinterpret_cast<uint32_t*>(&h);
}
__device__ __forceinline__ uint32_t smem_u32(const void* p) {
    uint32_t a;
    asm("{ .reg .u64 t; cvta.to.shared.u64 t, %1; cvt.u32.u64 %0, t; }"
        : "=r"(a) : "l"(p));
    return a;
}
__device__ __forceinline__ void cpa16(uint32_t dst, const void* src) {
    asm volatile("cp.async.cg.shared.global [%0], [%1], 16;"
                 :: "r"(dst), "l"(src) : "memory");
}
#define CP_COMMIT() asm volatile("cp.async.commit_group;" ::: "memory")
#define CP_WAIT0()  asm volatile("cp.async.wait_group 0;" ::: "memory")
#define CP_WAIT1()  asm volatile("cp.async.wait_group 1;" ::: "memory")

#define LDSM4(r, addr) \
    asm volatile("ldmatrix.sync.aligned.m8n8.x4.shared.b16 {%0,%1,%2,%3}, [%4];" \
        : "=r"((r)[0]), "=r"((r)[1]), "=r"((r)[2]), "=r"((r)[3]) : "r"(addr))

__device__ __forceinline__ float ex2f(float x) {
    float r;
    asm("ex2.approx.f32 %0, %1;" : "=f"(r) : "f"(x));
    return r;
}

__device__ __forceinline__ void mma16816(float* c, const uint32_t* a,
                                         uint32_t b0, uint32_t b1) {
    asm volatile(
        "mma.sync.aligned.m16n8k16.row.col.f32.bf16.bf16.f32 "
        "{%0,%1,%2,%3}, {%4,%5,%6,%7}, {%8,%9}, {%0,%1,%2,%3};"
        : "+f"(c[0]), "+f"(c[1]), "+f"(c[2]), "+f"(c[3])
        : "r"(a[0]), "r"(a[1]), "r"(a[2]), "r"(a[3]), "r"(b0), "r"(b1));
}

// ---------------------------------------------------------------------------
// Elementwise fp32 -> bf16 hi/lo split
// ---------------------------------------------------------------------------
__global__ void split_kernel(const float* __restrict__ src,
                             __nv_bfloat16* __restrict__ dh,
                             __nv_bfloat16* __restrict__ dl, int n4) {
    int i = blockIdx.x * blockDim.x + threadIdx.x;
    int stride = gridDim.x * blockDim.x;
    for (; i < n4; i += stride) {
        float4 v = ((const float4*)src)[i];
        __nv_bfloat162 h01 = __floats2bfloat162_rn(v.x, v.y);
        __nv_bfloat162 h23 = __floats2bfloat162_rn(v.z, v.w);
        __nv_bfloat162 l01 = __floats2bfloat162_rn(v.x - __bfloat162float(h01.x),
                                                   v.y - __bfloat162float(h01.y));
        __nv_bfloat162 l23 = __floats2bfloat162_rn(v.z - __bfloat162float(h23.x),
                                                   v.w - __bfloat162float(h23.y));
        ((uint2*)dh)[i] = make_uint2(b2u(h01), b2u(h23));
        ((uint2*)dl)[i] = make_uint2(b2u(l01), b2u(l23));
    }
}

// ---------------------------------------------------------------------------
// Split-bf16 NT GEMM (R7-verified config): cp.async double-buffer, ldmatrix,
// 2 CTAs/SM. C[m,n] = sum_k A[m,k]*B[n,k]. 128x128 tile, K-chunk 32,
// 8 warps 4x2, smem rows padded to 80B (LDSM conflict-free).
// EPI=0: write Q/K/V split bf16 (V transposed). EPI=1: out = C + bias (fp32).
// ---------------------------------------------------------------------------
#define APAD_B 80
#define TILE_B (128 * APAD_B)              // 10240
#define BUF_B  (4 * TILE_B)                // AH, AL, BH, BL = 40960
#define GEMM_SMEM (2 * BUF_B)              // 81920
#define NCHUNK (CC / 32)                   // 32

template <int EPI>
__global__ __launch_bounds__(256, 2) void tc_gemm(
    const __nv_bfloat16* __restrict__ AH, const __nv_bfloat16* __restrict__ AL,
    const __nv_bfloat16* __restrict__ BH, const __nv_bfloat16* __restrict__ BL,
    const float* __restrict__ bias, float* __restrict__ out) {
    extern __shared__ char smc[];
    const uint32_t smb = smem_u32(smc);
    const int tid = threadIdx.x;
    const int m0 = blockIdx.y * 128;
    const int n0 = blockIdx.x * 128;
    const int wid = tid >> 5;
    const int lane = tid & 31;
    const int gid = lane >> 2;
    const int tig = lane & 3;
    const int wm = wid & 3;
    const int wn = wid >> 2;

    // ldmatrix.x4 per-lane offsets
    const uint32_t laneA = (uint32_t)(((lane & 7) + ((lane >> 3) & 1) * 8) * APAD_B
                                      + (lane >> 4) * 16);
    const uint32_t laneB = (uint32_t)(((lane & 7) + ((lane >> 4) & 1) * 8) * APAD_B
                                      + ((lane >> 3) & 1) * 16);

    float acc[2][8][4];
#pragma unroll
    for (int i = 0; i < 2; i++)
#pragma unroll
        for (int j = 0; j < 8; j++)
#pragma unroll
            for (int q = 0; q < 4; q++) acc[i][j][q] = 0.f;

    auto copyc = [&](int kk, int bufi) {
        uint32_t bbase = smb + bufi * BUF_B;
#pragma unroll
        for (int l = 0; l < 8; l++) {
            const int tile = l >> 1;
            int e2 = (l & 1) * 256 + tid;
            int r = e2 >> 2;
            int q = e2 & 3;
            const __nv_bfloat16* src =
                (tile == 0) ? AH : (tile == 1) ? AL : (tile == 2) ? BH : BL;
            int row = (tile < 2 ? m0 : n0) + r;
            cpa16(bbase + tile * TILE_B + r * APAD_B + q * 16,
                  src + (size_t)row * CC + kk + q * 8);
        }
    };

    auto compute = [&](uint32_t bufu) {
#pragma unroll
        for (int ks = 0; ks < 2; ks++) {
            uint32_t ah[2][4], al[2][4];
#pragma unroll
            for (int i = 0; i < 2; i++) {
                uint32_t aaddr = bufu + laneA + (wm * 32 + i * 16) * APAD_B + ks * 32;
                LDSM4(ah[i], aaddr);
                LDSM4(al[i], aaddr + TILE_B);
            }
#pragma unroll
            for (int jp = 0; jp < 4; jp++) {
                uint32_t baddr = bufu + 2 * TILE_B + laneB
                               + (wn * 64 + jp * 16) * APAD_B + ks * 32;
                uint32_t rh[4], rl[4];
                LDSM4(rh, baddr);
                LDSM4(rl, baddr + TILE_B);
#pragma unroll
                for (int t = 0; t < 2; t++) {
                    int j = 2 * jp + t;
#pragma unroll
                    for (int i = 0; i < 2; i++) {
                        mma16816(acc[i][j], ah[i], rh[2 * t], rh[2 * t + 1]);
                        mma16816(acc[i][j], ah[i], rl[2 * t], rl[2 * t + 1]);
                        mma16816(acc[i][j], al[i], rh[2 * t], rh[2 * t + 1]);
                    }
                }
            }
        }
    };

    copyc(0, 0);
    CP_COMMIT();
    for (int c = 0; c < NCHUNK; c++) {
        if (c + 1 < NCHUNK) {
            copyc((c + 1) * 32, (c + 1) & 1);
            CP_COMMIT();
            CP_WAIT1();
        } else {
            CP_WAIT0();
        }
        __syncthreads();
        compute(smb + (uint32_t)(c & 1) * BUF_B);
        __syncthreads();
    }

    // ---- epilogue: fragments -> smem staging
    float* Ds = (float*)smc;               // 128 x 132 f32 = 67584 <= 81920
#pragma unroll
    for (int i = 0; i < 2; i++) {
        int rr = wm * 32 + i * 16 + gid;
#pragma unroll
        for (int j = 0; j < 8; j++) {
            int cc = wn * 64 + j * 8 + tig * 2;
            *(float2*)&Ds[rr * 132 + cc]       = make_float2(acc[i][j][0], acc[i][j][1]);
            *(float2*)&Ds[(rr + 8) * 132 + cc] = make_float2(acc[i][j][2], acc[i][j][3]);
        }
    }
    __syncthreads();

    if (EPI == 1) {
#pragma unroll 4
        for (int ll = 0; ll < 64; ll++) {
            int flat = ll * 256 + tid;
            int n = flat & 127;
            int m = flat >> 7;
            out[(size_t)(m0 + m) * CC + n0 + n] = Ds[m * 132 + n] + bias[n0 + n];
        }
    } else {
#pragma unroll
        for (int seg = 0; seg < 2; seg++) {
            int gn0 = n0 + seg * 64;
            int h = gn0 / 192;
            int part = (gn0 % 192) >> 6;
            if (part < 2) {
                __nv_bfloat16* dh = (part == 0) ? g_qh : g_kh;
                __nv_bfloat16* dl = (part == 0) ? g_ql : g_kl;
#pragma unroll
                for (int it = 0; it < 16; it++) {
                    int m = it * 8 + (tid >> 5);
                    int d2 = (tid & 31) * 2;
                    float v0 = Ds[m * 132 + seg * 64 + d2];
                    float v1 = Ds[m * 132 + seg * 64 + d2 + 1];
                    __nv_bfloat162 hp = __floats2bfloat162_rn(v0, v1);
                    __nv_bfloat162 lp = __floats2bfloat162_rn(
                        v0 - __bfloat162float(hp.x), v1 - __bfloat162float(hp.y));
                    int gm = m0 + m; int b = gm >> 11; int t = gm & 2047;
                    size_t idx = (((size_t)(b * HH + h)) * TT + t) * HD + d2;
                    *(__nv_bfloat162*)(dh + idx) = hp;
                    *(__nv_bfloat162*)(dl + idx) = lp;
                }
            } else {                        // V: transposed [bh][d][t]
#pragma unroll
                for (int it = 0; it < 16; it++) {
                    int flat = it * 256 + tid;     // 0..4095
                    int d = flat >> 6;             // 0..63
                    int tp = (flat & 63) * 2;      // 0..126 (pair along t)
                    float v0 = Ds[tp * 132 + seg * 64 + d];
                    float v1 = Ds[(tp + 1) * 132 + seg * 64 + d];
                    __nv_bfloat162 hp = __floats2bfloat162_rn(v0, v1);
                    __nv_bfloat162 lp = __floats2bfloat162_rn(
                        v0 - __bfloat162float(hp.x), v1 - __bfloat162float(hp.y));
                    int gm = m0 + tp; int b = gm >> 11; int t = gm & 2047;
                    size_t idx = (((size_t)(b * HH + h)) * HD + d) * TT + t;
                    *(__nv_bfloat162*)(g_vh + idx) = hp;
                    *(__nv_bfloat162*)(g_vl + idx) = lp;
                }
            }
        }
    }
}

// ---------------------------------------------------------------------------
// Flash attention, split-bf16 mma + ldmatrix. BM=128 (8 warps x 16 rows),
// BN=64. 2 CTAs/SM (launch_bounds 128-reg cap; P packed per-ks to cut
// register peak). Softmax in base-2 domain (scale folds log2e). Heavy
// (high-q0) tiles scheduled first.
// ---------------------------------------------------------------------------
#define AT_ROW 144
#define AT_TILE (64 * AT_ROW)              // 9216
#define AT_BUF (4 * AT_TILE)               // 36864
#define ATT_SMEM_BYTES (2 * AT_BUF)        // 73728
#define SCL2 0.1803368801111137f           // 0.125 * log2(e)

__global__ __launch_bounds__(256, 2) void attn_kernel() {
    extern __shared__ char smc[];
    const uint32_t smb = smem_u32(smc);
    const int tid = threadIdx.x;
    const int bh = blockIdx.y;
    const int q0 = (gridDim.x - 1 - blockIdx.x) * 128;   // heavy tiles first
    const int wid = tid >> 5;
    const int lane = tid & 31;
    const int gid = lane >> 2;
    const int tig = lane & 3;
    const int r0 = q0 + wid * 16 + gid;

    const __nv_bfloat16* Qh = g_qh + (size_t)bh * TT * HD;
    const __nv_bfloat16* Ql = g_ql + (size_t)bh * TT * HD;
    const __nv_bfloat16* Kh = g_kh + (size_t)bh * TT * HD;
    const __nv_bfloat16* Kl = g_kl + (size_t)bh * TT * HD;
    const __nv_bfloat16* Vh = g_vh + (size_t)bh * HD * TT;
    const __nv_bfloat16* Vl = g_vl + (size_t)bh * HD * TT;

    const uint32_t laneB = (uint32_t)(((lane & 7) + ((lane >> 4) & 1) * 8) * AT_ROW
                                      + ((lane >> 3) & 1) * 16);

    // ---- Q fragments (pre-split), direct ldg
    uint32_t qh[4][4], ql[4][4];
#pragma unroll
    for (int ks = 0; ks < 4; ks++)
#pragma unroll
        for (int hv = 0; hv < 2; hv++)
#pragma unroll
            for (int rr = 0; rr < 2; rr++) {
                size_t o = (size_t)(r0 + rr * 8) * HD + ks * 16 + hv * 8 + tig * 2;
                qh[ks][hv * 2 + rr] = *(const uint32_t*)(Qh + o);
                ql[ks][hv * 2 + rr] = *(const uint32_t*)(Ql + o);
            }

    float oacc[8][4];
#pragma unroll
    for (int j = 0; j < 8; j++)
#pragma unroll
        for (int q = 0; q < 4; q++) oacc[j][q] = 0.f;
    float mr0 = -1e30f, mr1 = -1e30f, lr0 = 0.f, lr1 = 0.f;

    auto copyc = [&](int c, int bufi) {
        const int k0 = c * 64;
        uint32_t bbase = smb + bufi * AT_BUF;
#pragma unroll
        for (int l = 0; l < 8; l++) {
            const int tile = l >> 1;
            int e2 = (l & 1) * 256 + tid;
            int r = e2 >> 3;
            int q = e2 & 7;
            const __nv_bfloat16* src;
            if (tile == 0)      src = Kh + (size_t)(k0 + r) * HD + q * 8;
            else if (tile == 1) src = Kl + (size_t)(k0 + r) * HD + q * 8;
            else if (tile == 2) src = Vh + (size_t)r * TT + k0 + q * 8;
            else                src = Vl + (size_t)r * TT + k0 + q * 8;
            cpa16(bbase + tile * AT_TILE + r * AT_ROW + q * 16, src);
        }
    };

    const int jmax = (q0 >> 6) + 2;
    copyc(0, 0);
    CP_COMMIT();
    for (int c = 0; c < jmax; c++) {
        if (c + 1 < jmax) {
            copyc(c + 1, (c + 1) & 1);
            CP_COMMIT();
            CP_WAIT1();
        } else {
            CP_WAIT0();
        }
        __syncthreads();
        const uint32_t KT = smb + (uint32_t)(c & 1) * AT_BUF;
        const uint32_t VT = KT + 2 * AT_TILE;

        // ---- S = Q K^T (qh*kh + qh*kl + ql*kh)
        float s[8][4];
#pragma unroll
        for (int j = 0; j < 8; j++)
#pragma unroll
            for (int q = 0; q < 4; q++) s[j][q] = 0.f;
#pragma unroll
        for (int ks = 0; ks < 4; ks++) {
#pragma unroll
            for (int jp = 0; jp < 4; jp++) {
                uint32_t kaddr = KT + laneB + jp * 16 * AT_ROW + ks * 32;
                uint32_t rh[4], rl[4];
                LDSM4(rh, kaddr);
                LDSM4(rl, kaddr + AT_TILE);
#pragma unroll
                for (int t = 0; t < 2; t++) {
                    int j = 2 * jp + t;
                    mma16816(s[j], qh[ks], rh[2 * t], rh[2 * t + 1]);
                    mma16816(s[j], qh[ks], rl[2 * t], rl[2 * t + 1]);
                    mma16816(s[j], ql[ks], rh[2 * t], rh[2 * t + 1]);
                }
            }
        }

        // scale into base-2 logit domain
        const int k0 = c * 64;
#pragma unroll
        for (int j = 0; j < 8; j++)
#pragma unroll
            for (int q = 0; q < 4; q++) s[j][q] *= SCL2;
        if (c >= jmax - 2) {
#pragma unroll
            for (int j = 0; j < 8; j++) {
                int col = k0 + 8 * j + 2 * tig;
                if (col > r0)          s[j][0] = -1e30f;
                if (col + 1 > r0)      s[j][1] = -1e30f;
                if (col > r0 + 8)      s[j][2] = -1e30f;
                if (col + 1 > r0 + 8)  s[j][3] = -1e30f;
            }
        }

        // ---- online softmax (base-2)
        float pm0 = -1e30f, pm1 = -1e30f;
#pragma unroll
        for (int j = 0; j < 8; j++) {
            pm0 = fmaxf(pm0, fmaxf(s[j][0], s[j][1]));
            pm1 = fmaxf(pm1, fmaxf(s[j][2], s[j][3]));
        }
        pm0 = fmaxf(pm0, __shfl_xor_sync(0xffffffffu, pm0, 1));
        pm0 = fmaxf(pm0, __shfl_xor_sync(0xffffffffu, pm0, 2));
        pm1 = fmaxf(pm1, __shfl_xor_sync(0xffffffffu, pm1, 1));
        pm1 = fmaxf(pm1, __shfl_xor_sync(0xffffffffu, pm1, 2));
        float mn0 = fmaxf(mr0, pm0), mn1 = fmaxf(mr1, pm1);
        float a0 = ex2f(mr0 - mn0), a1 = ex2f(mr1 - mn1);
        float sum0 = 0.f, sum1 = 0.f;
#pragma unroll
        for (int j = 0; j < 8; j++) {
            s[j][0] = ex2f(s[j][0] - mn0);
            s[j][1] = ex2f(s[j][1] - mn0);
            s[j][2] = ex2f(s[j][2] - mn1);
            s[j][3] = ex2f(s[j][3] - mn1);
            sum0 += s[j][0] + s[j][1];
            sum1 += s[j][2] + s[j][3];
        }
        sum0 += __shfl_xor_sync(0xffffffffu, sum0, 1);
        sum0 += __shfl_xor_sync(0xffffffffu, sum0, 2);
        sum1 += __shfl_xor_sync(0xffffffffu, sum1, 1);
        sum1 += __shfl_xor_sync(0xffffffffu, sum1, 2);
        lr0 = lr0 * a0 + sum0;
        lr1 = lr1 * a1 + sum1;
        mr0 = mn0; mr1 = mn1;
#pragma unroll
        for (int j = 0; j < 8; j++) {
            oacc[j][0] *= a0; oacc[j][1] *= a0;
            oacc[j][2] *= a1; oacc[j][3] *= a1;
        }

        // ---- O += P V, packing P per-ks (keeps register peak low)
#pragma unroll
        for (int ks = 0; ks < 4; ks++) {
            uint32_t pah[4], pal[4];
            int j0 = 2 * ks, j1 = 2 * ks + 1;
#pragma unroll
            for (int part = 0; part < 4; part++) {
                int jj = (part < 2) ? j0 : j1;
                int qa = (part & 1) * 2;
                float x = s[jj][qa], y = s[jj][qa + 1];
                __nv_bfloat162 hp = __floats2bfloat162_rn(x, y);
                __nv_bfloat162 lp = __floats2bfloat162_rn(
                    x - __bfloat162float(hp.x), y - __bfloat162float(hp.y));
                pah[part] = b2u(hp);
                pal[part] = b2u(lp);
            }
#pragma unroll
            for (int jp = 0; jp < 4; jp++) {
                uint32_t vaddr = VT + laneB + jp * 16 * AT_ROW + ks * 32;
                uint32_t rh[4], rl[4];
                LDSM4(rh, vaddr);
                LDSM4(rl, vaddr + AT_TILE);
#pragma unroll
                for (int t = 0; t < 2; t++) {
                    int j = 2 * jp + t;
                    mma16816(oacc[j], pah, rh[2 * t], rh[2 * t + 1]);
                    mma16816(oacc[j], pah, rl[2 * t], rl[2 * t + 1]);
                    mma16816(oacc[j], pal, rh[2 * t], rh[2 * t + 1]);
                }
            }
        }
        __syncthreads();
    }

    // ---- epilogue: normalize, split bf16, write g_ah/g_al [B,T,C]
    const int b = bh >> 4;
    const int h = bh & 15;
    float inv0 = 1.f / lr0, inv1 = 1.f / lr1;
#pragma unroll
    for (int j = 0; j < 8; j++) {
        int d = 8 * j + 2 * tig;
        size_t o0 = ((size_t)(b * TT + r0)) * CC + h * HD + d;
        size_t o1 = ((size_t)(b * TT + r0 + 8)) * CC + h * HD + d;
        float x0 = oacc[j][0] * inv0, y0 = oacc[j][1] * inv0;
        float x1 = oacc[j][2] * inv1, y1 = oacc[j][3] * inv1;
        __nv_bfloat162 h0 = __floats2bfloat162_rn(x0, y0);
        __nv_bfloat162 l0 = __floats2bfloat162_rn(x0 - __bfloat162float(h0.x),
                                                  y0 - __bfloat162float(h0.y));
        __nv_bfloat162 h1 = __floats2bfloat162_rn(x1, y1);
        __nv_bfloat162 l1 = __floats2bfloat162_rn(x1 - __bfloat162float(h1.x),
                                                  y1 - __bfloat162float(h1.y));
        *(__nv_bfloat162*)(g_ah + o0) = h0;
        *(__nv_bfloat162*)(g_al + o0) = l0;
        *(__nv_bfloat162*)(g_ah + o1) = h1;
        *(__nv_bfloat162*)(g_al + o1) = l1;
    }
}

// ---------------------------------------------------------------------------

extern "C" void kernel_launch(void* const* d_in, const int* in_sizes, int n_in,
                              void* d_out, int out_size) {
    const float* x      = (const float*)d_in[0];
    const float* w_qkv  = (const float*)d_in[1];
    const float* w_proj = (const float*)d_in[2];
    const float* b_proj = (const float*)d_in[3];
    float* out = (float*)d_out;

    __nv_bfloat16 *xh, *xl, *wqh, *wql, *wph, *wpl, *ah, *al;
    cudaGetSymbolAddress((void**)&xh,  g_xh);
    cudaGetSymbolAddress((void**)&xl,  g_xl);
    cudaGetSymbolAddress((void**)&wqh, g_wqh);
    cudaGetSymbolAddress((void**)&wql, g_wql);
    cudaGetSymbolAddress((void**)&wph, g_wph);
    cudaGetSymbolAddress((void**)&wpl, g_wpl);
    cudaGetSymbolAddress((void**)&ah,  g_ah);
    cudaGetSymbolAddress((void**)&al,  g_al);

    cudaFuncSetAttribute(tc_gemm<0>, cudaFuncAttributeMaxDynamicSharedMemorySize, GEMM_SMEM);
    cudaFuncSetAttribute(tc_gemm<1>, cudaFuncAttributeMaxDynamicSharedMemorySize, GEMM_SMEM);
    cudaFuncSetAttribute(attn_kernel, cudaFuncAttributeMaxDynamicSharedMemorySize, ATT_SMEM_BYTES);

    split_kernel<<<2048, 256>>>(x, xh, xl, MROWS * CC / 4);
    split_kernel<<<2048, 256>>>(w_qkv, wqh, wql, N_QKV * CC / 4);
    split_kernel<<<1024, 256>>>(w_proj, wph, wpl, CC * CC / 4);

    tc_gemm<0><<<dim3(N_QKV / 128, MROWS / 128), 256, GEMM_SMEM>>>(
        xh, xl, wqh, wql, nullptr, nullptr);
    attn_kernel<<<dim3(TT / 128, BB * HH), 256, ATT_SMEM_BYTES>>>();
    tc_gemm<1><<<dim3(CC / 128, MROWS / 128), 256, GEMM_SMEM>>>(
        ah, al, wph, wpl, b_proj, out);
}

// round 12
// speedup vs baseline: 1.6489x; 1.1161x over previous
#include <cuda_runtime.h>
#include <cuda_bf16.h>
#include <cuda_fp16.h>
#include <math.h>
#include <stdint.h>

// Problem constants
#define BB 4
#define TT 2048
#define CC 1024
#define HH 16
#define HD 64
#define MROWS (BB * TT)          // 8192
#define N_QKV (3 * CC)           // 3072

// ---------------------------------------------------------------------------
// Global scratch (allocation-free)
// ---------------------------------------------------------------------------
__device__ __nv_bfloat16 g_xh[MROWS * CC],  g_xl[MROWS * CC];
__device__ __nv_bfloat16 g_wqh[N_QKV * CC], g_wql[N_QKV * CC];
__device__ __nv_bfloat16 g_wph[CC * CC],    g_wpl[CC * CC];
__device__ __half        g_qf[BB * HH * TT * HD];                          // [bh][t][d] fp16
__device__ __half        g_kf[BB * HH * TT * HD];                          // [bh][t][d] fp16
__device__ __nv_bfloat16 g_vh[BB * HH * TT * HD], g_vl[BB * HH * TT * HD]; // [bh][d][t]
__device__ __nv_bfloat16 g_ah[MROWS * CC],  g_al[MROWS * CC];              // att out [B,T,C]

// ---------------------------------------------------------------------------
// Helpers
// ---------------------------------------------------------------------------
__device__ __forceinline__ uint32_t b2u(__nv_bfloat162 h) {
    return *reinterpret_cast<uint32_t*>(&h);
}
__device__ __forceinline__ uint32_t h2u(__half2 h) {
    return *reinterpret_cast<uint32_t*>(&h);
}
__device__ __forceinline__ uint32_t smem_u32(const void* p) {
    uint32_t a;
    asm("{ .reg .u64 t; cvta.to.shared.u64 t, %1; cvt.u32.u64 %0, t; }"
        : "=r"(a) : "l"(p));
    return a;
}
__device__ __forceinline__ void cpa16(uint32_t dst, const void* src) {
    asm volatile("cp.async.cg.shared.global [%0], [%1], 16;"
                 :: "r"(dst), "l"(src) : "memory");
}
#define CP_COMMIT() asm volatile("cp.async.commit_group;" ::: "memory")
#define CP_WAIT0()  asm volatile("cp.async.wait_group 0;" ::: "memory")
#define CP_WAIT1()  asm volatile("cp.async.wait_group 1;" ::: "memory")

#define LDSM4(r, addr) \
    asm volatile("ldmatrix.sync.aligned.m8n8.x4.shared.b16 {%0,%1,%2,%3}, [%4];" \
        : "=r"((r)[0]), "=r"((r)[1]), "=r"((r)[2]), "=r"((r)[3]) : "r"(addr))

__device__ __forceinline__ float ex2f(float x) {
    float r;
    asm("ex2.approx.f32 %0, %1;" : "=f"(r) : "f"(x));
    return r;
}

__device__ __forceinline__ void mma16816(float* c, const uint32_t* a,
                                         uint32_t b0, uint32_t b1) {
    asm volatile(
        "mma.sync.aligned.m16n8k16.row.col.f32.bf16.bf16.f32 "
        "{%0,%1,%2,%3}, {%4,%5,%6,%7}, {%8,%9}, {%0,%1,%2,%3};"
        : "+f"(c[0]), "+f"(c[1]), "+f"(c[2]), "+f"(c[3])
        : "r"(a[0]), "r"(a[1]), "r"(a[2]), "r"(a[3]), "r"(b0), "r"(b1));
}
__device__ __forceinline__ void mma16816h(float* c, const uint32_t* a,
                                          uint32_t b0, uint32_t b1) {
    asm volatile(
        "mma.sync.aligned.m16n8k16.row.col.f32.f16.f16.f32 "
        "{%0,%1,%2,%3}, {%4,%5,%6,%7}, {%8,%9}, {%0,%1,%2,%3};"
        : "+f"(c[0]), "+f"(c[1]), "+f"(c[2]), "+f"(c[3])
        : "r"(a[0]), "r"(a[1]), "r"(a[2]), "r"(a[3]), "r"(b0), "r"(b1));
}

// ---------------------------------------------------------------------------
// Elementwise fp32 -> bf16 hi/lo split
// ---------------------------------------------------------------------------
__global__ void split_kernel(const float* __restrict__ src,
                             __nv_bfloat16* __restrict__ dh,
                             __nv_bfloat16* __restrict__ dl, int n4) {
    int i = blockIdx.x * blockDim.x + threadIdx.x;
    int stride = gridDim.x * blockDim.x;
    for (; i < n4; i += stride) {
        float4 v = ((const float4*)src)[i];
        __nv_bfloat162 h01 = __floats2bfloat162_rn(v.x, v.y);
        __nv_bfloat162 h23 = __floats2bfloat162_rn(v.z, v.w);
        __nv_bfloat162 l01 = __floats2bfloat162_rn(v.x - __bfloat162float(h01.x),
                                                   v.y - __bfloat162float(h01.y));
        __nv_bfloat162 l23 = __floats2bfloat162_rn(v.z - __bfloat162float(h23.x),
                                                   v.w - __bfloat162float(h23.y));
        ((uint2*)dh)[i] = make_uint2(b2u(h01), b2u(h23));
        ((uint2*)dl)[i] = make_uint2(b2u(l01), b2u(l23));
    }
}

// ---------------------------------------------------------------------------
// Split-bf16 NT GEMM (R7-verified config): cp.async double-buffer, ldmatrix,
// 2 CTAs/SM. C[m,n] = sum_k A[m,k]*B[n,k]. 128x128 tile, K-chunk 32,
// 8 warps 4x2, smem rows padded to 80B (LDSM conflict-free).
// EPI=0: write Q/K fp16 + V split bf16 transposed. EPI=1: out = C + bias.
// ---------------------------------------------------------------------------
#define APAD_B 80
#define TILE_B (128 * APAD_B)              // 10240
#define BUF_B  (4 * TILE_B)                // AH, AL, BH, BL = 40960
#define GEMM_SMEM (2 * BUF_B)              // 81920
#define NCHUNK (CC / 32)                   // 32

template <int EPI>
__global__ __launch_bounds__(256, 2) void tc_gemm(
    const __nv_bfloat16* __restrict__ AH, const __nv_bfloat16* __restrict__ AL,
    const __nv_bfloat16* __restrict__ BH, const __nv_bfloat16* __restrict__ BL,
    const float* __restrict__ bias, float* __restrict__ out) {
    extern __shared__ char smc[];
    const uint32_t smb = smem_u32(smc);
    const int tid = threadIdx.x;
    const int m0 = blockIdx.y * 128;
    const int n0 = blockIdx.x * 128;
    const int wid = tid >> 5;
    const int lane = tid & 31;
    const int gid = lane >> 2;
    const int tig = lane & 3;
    const int wm = wid & 3;
    const int wn = wid >> 2;

    const uint32_t laneA = (uint32_t)(((lane & 7) + ((lane >> 3) & 1) * 8) * APAD_B
                                      + (lane >> 4) * 16);
    const uint32_t laneB = (uint32_t)(((lane & 7) + ((lane >> 4) & 1) * 8) * APAD_B
                                      + ((lane >> 3) & 1) * 16);

    float acc[2][8][4];
#pragma unroll
    for (int i = 0; i < 2; i++)
#pragma unroll
        for (int j = 0; j < 8; j++)
#pragma unroll
            for (int q = 0; q < 4; q++) acc[i][j][q] = 0.f;

    auto copyc = [&](int kk, int bufi) {
        uint32_t bbase = smb + bufi * BUF_B;
#pragma unroll
        for (int l = 0; l < 8; l++) {
            const int tile = l >> 1;
            int e2 = (l & 1) * 256 + tid;
            int r = e2 >> 2;
            int q = e2 & 3;
            const __nv_bfloat16* src =
                (tile == 0) ? AH : (tile == 1) ? AL : (tile == 2) ? BH : BL;
            int row = (tile < 2 ? m0 : n0) + r;
            cpa16(bbase + tile * TILE_B + r * APAD_B + q * 16,
                  src + (size_t)row * CC + kk + q * 8);
        }
    };

    auto compute = [&](uint32_t bufu) {
#pragma unroll
        for (int ks = 0; ks < 2; ks++) {
            uint32_t ah[2][4], al[2][4];
#pragma unroll
            for (int i = 0; i < 2; i++) {
                uint32_t aaddr = bufu + laneA + (wm * 32 + i * 16) * APAD_B + ks * 32;
                LDSM4(ah[i], aaddr);
                LDSM4(al[i], aaddr + TILE_B);
            }
#pragma unroll
            for (int jp = 0; jp < 4; jp++) {
                uint32_t baddr = bufu + 2 * TILE_B + laneB
                               + (wn * 64 + jp * 16) * APAD_B + ks * 32;
                uint32_t rh[4], rl[4];
                LDSM4(rh, baddr);
                LDSM4(rl, baddr + TILE_B);
#pragma unroll
                for (int t = 0; t < 2; t++) {
                    int j = 2 * jp + t;
#pragma unroll
                    for (int i = 0; i < 2; i++) {
                        mma16816(acc[i][j], ah[i], rh[2 * t], rh[2 * t + 1]);
                        mma16816(acc[i][j], ah[i], rl[2 * t], rl[2 * t + 1]);
                        mma16816(acc[i][j], al[i], rh[2 * t], rh[2 * t + 1]);
                    }
                }
            }
        }
    };

    copyc(0, 0);
    CP_COMMIT();
    for (int c = 0; c < NCHUNK; c++) {
        if (c + 1 < NCHUNK) {
            copyc((c + 1) * 32, (c + 1) & 1);
            CP_COMMIT();
            CP_WAIT1();
        } else {
            CP_WAIT0();
        }
        __syncthreads();
        compute(smb + (uint32_t)(c & 1) * BUF_B);
        __syncthreads();
    }

    // ---- epilogue: fragments -> smem staging
    float* Ds = (float*)smc;               // 128 x 132 f32 = 67584 <= 81920
#pragma unroll
    for (int i = 0; i < 2; i++) {
        int rr = wm * 32 + i * 16 + gid;
#pragma unroll
        for (int j = 0; j < 8; j++) {
            int cc = wn * 64 + j * 8 + tig * 2;
            *(float2*)&Ds[rr * 132 + cc]       = make_float2(acc[i][j][0], acc[i][j][1]);
            *(float2*)&Ds[(rr + 8) * 132 + cc] = make_float2(acc[i][j][2], acc[i][j][3]);
        }
    }
    __syncthreads();

    if (EPI == 1) {
#pragma unroll 4
        for (int ll = 0; ll < 64; ll++) {
            int flat = ll * 256 + tid;
            int n = flat & 127;
            int m = flat >> 7;
            out[(size_t)(m0 + m) * CC + n0 + n] = Ds[m * 132 + n] + bias[n0 + n];
        }
    } else {
        // two 64-wide segments; each wholly one of q/k/v (192 % 64 == 0)
#pragma unroll
        for (int seg = 0; seg < 2; seg++) {
            int gn0 = n0 + seg * 64;
            int h = gn0 / 192;
            int part = (gn0 % 192) >> 6;
            if (part < 2) {
                __half* dst = (part == 0) ? g_qf : g_kf;   // fp16, single
#pragma unroll
                for (int it = 0; it < 16; it++) {
                    int m = it * 8 + (tid >> 5);
                    int d2 = (tid & 31) * 2;
                    float v0 = Ds[m * 132 + seg * 64 + d2];
                    float v1 = Ds[m * 132 + seg * 64 + d2 + 1];
                    __half2 hp = __floats2half2_rn(v0, v1);
                    int gm = m0 + m; int b = gm >> 11; int t = gm & 2047;
                    size_t idx = (((size_t)(b * HH + h)) * TT + t) * HD + d2;
                    *(uint32_t*)(dst + idx) = h2u(hp);
                }
            } else {                        // V: transposed [bh][d][t], bf16 split
#pragma unroll
                for (int it = 0; it < 16; it++) {
                    int flat = it * 256 + tid;     // 0..4095
                    int d = flat >> 6;             // 0..63
                    int tp = (flat & 63) * 2;      // 0..126 (pair along t)
                    float v0 = Ds[tp * 132 + seg * 64 + d];
                    float v1 = Ds[(tp + 1) * 132 + seg * 64 + d];
                    __nv_bfloat162 hp = __floats2bfloat162_rn(v0, v1);
                    __nv_bfloat162 lp = __floats2bfloat162_rn(
                        v0 - __bfloat162float(hp.x), v1 - __bfloat162float(hp.y));
                    int gm = m0 + tp; int b = gm >> 11; int t = gm & 2047;
                    size_t idx = (((size_t)(b * HH + h)) * HD + d) * TT + t;
                    *(__nv_bfloat162*)(g_vh + idx) = hp;
                    *(__nv_bfloat162*)(g_vl + idx) = lp;
                }
            }
        }
    }
}

// ---------------------------------------------------------------------------
// Flash attention. S = Q K^T in single fp16 MMA (Q,K pre-stored fp16);
// PV in split-bf16 (3 products). BM=128 (8 warps x 16 rows), BN=64.
// 2 CTAs/SM; softmax in base-2; heavy (high-q0) tiles first.
// Smem per buffer: Kf (fp16) + Vh + Vl, rows padded to 144B.
// ---------------------------------------------------------------------------
#define AT_ROW 144
#define AT_TILE (64 * AT_ROW)              // 9216
#define AT_BUF (3 * AT_TILE)               // Kf, Vh, Vl = 27648
#define ATT_SMEM_BYTES (2 * AT_BUF)        // 55296
#define SCL2 0.1803368801111137f           // 0.125 * log2(e)

__global__ __launch_bounds__(256, 2) void attn_kernel() {
    extern __shared__ char smc[];
    const uint32_t smb = smem_u32(smc);
    const int tid = threadIdx.x;
    const int bh = blockIdx.y;
    const int q0 = (gridDim.x - 1 - blockIdx.x) * 128;   // heavy tiles first
    const int wid = tid >> 5;
    const int lane = tid & 31;
    const int gid = lane >> 2;
    const int tig = lane & 3;
    const int r0 = q0 + wid * 16 + gid;

    const __half*        Qf = g_qf + (size_t)bh * TT * HD;
    const __half*        Kf = g_kf + (size_t)bh * TT * HD;
    const __nv_bfloat16* Vh = g_vh + (size_t)bh * HD * TT;
    const __nv_bfloat16* Vl = g_vl + (size_t)bh * HD * TT;

    const uint32_t laneB = (uint32_t)(((lane & 7) + ((lane >> 4) & 1) * 8) * AT_ROW
                                      + ((lane >> 3) & 1) * 16);

    // ---- Q fragments (fp16, single), direct ldg
    uint32_t qf[4][4];
#pragma unroll
    for (int ks = 0; ks < 4; ks++)
#pragma unroll
        for (int hv = 0; hv < 2; hv++)
#pragma unroll
            for (int rr = 0; rr < 2; rr++) {
                size_t o = (size_t)(r0 + rr * 8) * HD + ks * 16 + hv * 8 + tig * 2;
                qf[ks][hv * 2 + rr] = *(const uint32_t*)(Qf + o);
            }

    float oacc[8][4];
#pragma unroll
    for (int j = 0; j < 8; j++)
#pragma unroll
        for (int q = 0; q < 4; q++) oacc[j][q] = 0.f;
    float mr0 = -1e30f, mr1 = -1e30f, lr0 = 0.f, lr1 = 0.f;

    auto copyc = [&](int c, int bufi) {
        const int k0 = c * 64;
        uint32_t bbase = smb + bufi * AT_BUF;
#pragma unroll
        for (int l = 0; l < 6; l++) {
            const int tile = l >> 1;            // 0=Kf, 1=Vh, 2=Vl
            int e2 = (l & 1) * 256 + tid;       // 0..511
            int r = e2 >> 3;                    // 0..63
            int q = e2 & 7;                     // 0..7
            const void* src;
            if (tile == 0)      src = Kf + (size_t)(k0 + r) * HD + q * 8;
            else if (tile == 1) src = Vh + (size_t)r * TT + k0 + q * 8;
            else                src = Vl + (size_t)r * TT + k0 + q * 8;
            cpa16(bbase + tile * AT_TILE + r * AT_ROW + q * 16, src);
        }
    };

    const int jmax = (q0 >> 6) + 2;
    copyc(0, 0);
    CP_COMMIT();
    for (int c = 0; c < jmax; c++) {
        if (c + 1 < jmax) {
            copyc(c + 1, (c + 1) & 1);
            CP_COMMIT();
            CP_WAIT1();
        } else {
            CP_WAIT0();
        }
        __syncthreads();
        const uint32_t KT = smb + (uint32_t)(c & 1) * AT_BUF;
        const uint32_t VT = KT + AT_TILE;

        // ---- S = Q K^T, single fp16 product
        float s[8][4];
#pragma unroll
        for (int j = 0; j < 8; j++)
#pragma unroll
            for (int q = 0; q < 4; q++) s[j][q] = 0.f;
#pragma unroll
        for (int ks = 0; ks < 4; ks++) {
#pragma unroll
            for (int jp = 0; jp < 4; jp++) {
                uint32_t kaddr = KT + laneB + jp * 16 * AT_ROW + ks * 32;
                uint32_t rk[4];
                LDSM4(rk, kaddr);
#pragma unroll
                for (int t = 0; t < 2; t++) {
                    int j = 2 * jp + t;
                    mma16816h(s[j], qf[ks], rk[2 * t], rk[2 * t + 1]);
                }
            }
        }

        // scale into base-2 logit domain
        const int k0 = c * 64;
#pragma unroll
        for (int j = 0; j < 8; j++)
#pragma unroll
            for (int q = 0; q < 4; q++) s[j][q] *= SCL2;
        if (c >= jmax - 2) {
#pragma unroll
            for (int j = 0; j < 8; j++) {
                int col = k0 + 8 * j + 2 * tig;
                if (col > r0)          s[j][0] = -1e30f;
                if (col + 1 > r0)      s[j][1] = -1e30f;
                if (col > r0 + 8)      s[j][2] = -1e30f;
                if (col + 1 > r0 + 8)  s[j][3] = -1e30f;
            }
        }

        // ---- online softmax (base-2)
        float pm0 = -1e30f, pm1 = -1e30f;
#pragma unroll
        for (int j = 0; j < 8; j++) {
            pm0 = fmaxf(pm0, fmaxf(s[j][0], s[j][1]));
            pm1 = fmaxf(pm1, fmaxf(s[j][2], s[j][3]));
        }
        pm0 = fmaxf(pm0, __shfl_xor_sync(0xffffffffu, pm0, 1));
        pm0 = fmaxf(pm0, __shfl_xor_sync(0xffffffffu, pm0, 2));
        pm1 = fmaxf(pm1, __shfl_xor_sync(0xffffffffu, pm1, 1));
        pm1 = fmaxf(pm1, __shfl_xor_sync(0xffffffffu, pm1, 2));
        float mn0 = fmaxf(mr0, pm0), mn1 = fmaxf(mr1, pm1);
        float a0 = ex2f(mr0 - mn0), a1 = ex2f(mr1 - mn1);
        float sum0 = 0.f, sum1 = 0.f;
#pragma unroll
        for (int j = 0; j < 8; j++) {
            s[j][0] = ex2f(s[j][0] - mn0);
            s[j][1] = ex2f(s[j][1] - mn0);
            s[j][2] = ex2f(s[j][2] - mn1);
            s[j][3] = ex2f(s[j][3] - mn1);
            sum0 += s[j][0] + s[j][1];
            sum1 += s[j][2] + s[j][3];
        }
        sum0 += __shfl_xor_sync(0xffffffffu, sum0, 1);
        sum0 += __shfl_xor_sync(0xffffffffu, sum0, 2);
        sum1 += __shfl_xor_sync(0xffffffffu, sum1, 1);
        sum1 += __shfl_xor_sync(0xffffffffu, sum1, 2);
        lr0 = lr0 * a0 + sum0;
        lr1 = lr1 * a1 + sum1;
        mr0 = mn0; mr1 = mn1;
#pragma unroll
        for (int j = 0; j < 8; j++) {
            oacc[j][0] *= a0; oacc[j][1] *= a0;
            oacc[j][2] *= a1; oacc[j][3] *= a1;
        }

        // ---- O += P V (bf16 split: ph*vh + ph*vl + pl*vh), P packed per-ks
#pragma unroll
        for (int ks = 0; ks < 4; ks++) {
            uint32_t pah[4], pal[4];
            int j0 = 2 * ks, j1 = 2 * ks + 1;
#pragma unroll
            for (int part = 0; part < 4; part++) {
                int jj = (part < 2) ? j0 : j1;
                int qa = (part & 1) * 2;
                float x = s[jj][qa], y = s[jj][qa + 1];
                __nv_bfloat162 hp = __floats2bfloat162_rn(x, y);
                __nv_bfloat162 lp = __floats2bfloat162_rn(
                    x - __bfloat162float(hp.x), y - __bfloat162float(hp.y));
                pah[part] = b2u(hp);
                pal[part] = b2u(lp);
            }
#pragma unroll
            for (int jp = 0; jp < 4; jp++) {
                uint32_t vaddr = VT + laneB + jp * 16 * AT_ROW + ks * 32;
                uint32_t rh[4], rl[4];
                LDSM4(rh, vaddr);
                LDSM4(rl, vaddr + AT_TILE);
#pragma unroll
                for (int t = 0; t < 2; t++) {
                    int j = 2 * jp + t;
                    mma16816(oacc[j], pah, rh[2 * t], rh[2 * t + 1]);
                    mma16816(oacc[j], pah, rl[2 * t], rl[2 * t + 1]);
                    mma16816(oacc[j], pal, rh[2 * t], rh[2 * t + 1]);
                }
            }
        }
        __syncthreads();
    }

    // ---- epilogue: normalize, split bf16, write g_ah/g_al [B,T,C]
    const int b = bh >> 4;
    const int h = bh & 15;
    float inv0 = 1.f / lr0, inv1 = 1.f / lr1;
#pragma unroll
    for (int j = 0; j < 8; j++) {
        int d = 8 * j + 2 * tig;
        size_t o0 = ((size_t)(b * TT + r0)) * CC + h * HD + d;
        size_t o1 = ((size_t)(b * TT + r0 + 8)) * CC + h * HD + d;
        float x0 = oacc[j][0] * inv0, y0 = oacc[j][1] * inv0;
        float x1 = oacc[j][2] * inv1, y1 = oacc[j][3] * inv1;
        __nv_bfloat162 h0 = __floats2bfloat162_rn(x0, y0);
        __nv_bfloat162 l0 = __floats2bfloat162_rn(x0 - __bfloat162float(h0.x),
                                                  y0 - __bfloat162float(h0.y));
        __nv_bfloat162 h1 = __floats2bfloat162_rn(x1, y1);
        __nv_bfloat162 l1 = __floats2bfloat162_rn(x1 - __bfloat162float(h1.x),
                                                  y1 - __bfloat162float(h1.y));
        *(__nv_bfloat162*)(g_ah + o0) = h0;
        *(__nv_bfloat162*)(g_al + o0) = l0;
        *(__nv_bfloat162*)(g_ah + o1) = h1;
        *(__nv_bfloat162*)(g_al + o1) = l1;
    }
}

// ---------------------------------------------------------------------------

extern "C" void kernel_launch(void* const* d_in, const int* in_sizes, int n_in,
                              void* d_out, int out_size) {
    const float* x      = (const float*)d_in[0];
    const float* w_qkv  = (const float*)d_in[1];
    const float* w_proj = (const float*)d_in[2];
    const float* b_proj = (const float*)d_in[3];
    float* out = (float*)d_out;

    __nv_bfloat16 *xh, *xl, *wqh, *wql, *wph, *wpl, *ah, *al;
    cudaGetSymbolAddress((void**)&xh,  g_xh);
    cudaGetSymbolAddress((void**)&xl,  g_xl);
    cudaGetSymbolAddress((void**)&wqh, g_wqh);
    cudaGetSymbolAddress((void**)&wql, g_wql);
    cudaGetSymbolAddress((void**)&wph, g_wph);
    cudaGetSymbolAddress((void**)&wpl, g_wpl);
    cudaGetSymbolAddress((void**)&ah,  g_ah);
    cudaGetSymbolAddress((void**)&al,  g_al);

    cudaFuncSetAttribute(tc_gemm<0>, cudaFuncAttributeMaxDynamicSharedMemorySize, GEMM_SMEM);
    cudaFuncSetAttribute(tc_gemm<1>, cudaFuncAttributeMaxDynamicSharedMemorySize, GEMM_SMEM);
    cudaFuncSetAttribute(attn_kernel, cudaFuncAttributeMaxDynamicSharedMemorySize, ATT_SMEM_BYTES);

    split_kernel<<<2048, 256>>>(x, xh, xl, MROWS * CC / 4);
    split_kernel<<<2048, 256>>>(w_qkv, wqh, wql, N_QKV * CC / 4);
    split_kernel<<<1024, 256>>>(w_proj, wph, wpl, CC * CC / 4);

    tc_gemm<0><<<dim3(N_QKV / 128, MROWS / 128), 256, GEMM_SMEM>>>(
        xh, xl, wqh, wql, nullptr, nullptr);
    attn_kernel<<<dim3(TT / 128, BB * HH), 256, ATT_SMEM_BYTES>>>();
    tc_gemm<1><<<dim3(CC / 128, MROWS / 128), 256, GEMM_SMEM>>>(
        ah, al, wph, wpl, b_proj, out);
}

// round 13
// speedup vs baseline: 1.8699x; 1.1340x over previous
#include <cuda_runtime.h>
#include <cuda_bf16.h>
#include <cuda_fp16.h>
#include <math.h>
#include <stdint.h>

// Problem constants
#define BB 4
#define TT 2048
#define CC 1024
#define HH 16
#define HD 64
#define MROWS (BB * TT)          // 8192
#define N_QKV (3 * CC)           // 3072

// ---------------------------------------------------------------------------
// Global scratch (allocation-free)
// ---------------------------------------------------------------------------
__device__ __nv_bfloat16 g_xh[MROWS * CC],  g_xl[MROWS * CC];
__device__ __nv_bfloat16 g_wqh[N_QKV * CC], g_wql[N_QKV * CC];
__device__ __half        g_wpf[CC * CC],    g_wpl[CC * CC];                // w_proj fp16 hi/lo
__device__ __half        g_qf[BB * HH * TT * HD];                          // [bh][t][d] fp16
__device__ __half        g_kf[BB * HH * TT * HD];                          // [bh][t][d] fp16
__device__ __half        g_vf[BB * HH * TT * HD], g_vl[BB * HH * TT * HD]; // [bh][d][t] fp16 hi/lo
__device__ __half        g_af[MROWS * CC];                                 // att out [B,T,C] fp16

// ---------------------------------------------------------------------------
// Helpers
// ---------------------------------------------------------------------------
__device__ __forceinline__ uint32_t b2u(__nv_bfloat162 h) {
    return *reinterpret_cast<uint32_t*>(&h);
}
__device__ __forceinline__ uint32_t h2u(__half2 h) {
    return *reinterpret_cast<uint32_t*>(&h);
}
__device__ __forceinline__ uint32_t smem_u32(const void* p) {
    uint32_t a;
    asm("{ .reg .u64 t; cvta.to.shared.u64 t, %1; cvt.u32.u64 %0, t; }"
        : "=r"(a) : "l"(p));
    return a;
}
__device__ __forceinline__ void cpa16(uint32_t dst, const void* src) {
    asm volatile("cp.async.cg.shared.global [%0], [%1], 16;"
                 :: "r"(dst), "l"(src) : "memory");
}
#define CP_COMMIT() asm volatile("cp.async.commit_group;" ::: "memory")
#define CP_WAIT0()  asm volatile("cp.async.wait_group 0;" ::: "memory")
#define CP_WAIT1()  asm volatile("cp.async.wait_group 1;" ::: "memory")

#define LDSM4(r, addr) \
    asm volatile("ldmatrix.sync.aligned.m8n8.x4.shared.b16 {%0,%1,%2,%3}, [%4];" \
        : "=r"((r)[0]), "=r"((r)[1]), "=r"((r)[2]), "=r"((r)[3]) : "r"(addr))

__device__ __forceinline__ float ex2f(float x) {
    float r;
    asm("ex2.approx.f32 %0, %1;" : "=f"(r) : "f"(x));
    return r;
}

__device__ __forceinline__ void mma16816(float* c, const uint32_t* a,
                                         uint32_t b0, uint32_t b1) {
    asm volatile(
        "mma.sync.aligned.m16n8k16.row.col.f32.bf16.bf16.f32 "
        "{%0,%1,%2,%3}, {%4,%5,%6,%7}, {%8,%9}, {%0,%1,%2,%3};"
        : "+f"(c[0]), "+f"(c[1]), "+f"(c[2]), "+f"(c[3])
        : "r"(a[0]), "r"(a[1]), "r"(a[2]), "r"(a[3]), "r"(b0), "r"(b1));
}
__device__ __forceinline__ void mma16816h(float* c, const uint32_t* a,
                                          uint32_t b0, uint32_t b1) {
    asm volatile(
        "mma.sync.aligned.m16n8k16.row.col.f32.f16.f16.f32 "
        "{%0,%1,%2,%3}, {%4,%5,%6,%7}, {%8,%9}, {%0,%1,%2,%3};"
        : "+f"(c[0]), "+f"(c[1]), "+f"(c[2]), "+f"(c[3])
        : "r"(a[0]), "r"(a[1]), "r"(a[2]), "r"(a[3]), "r"(b0), "r"(b1));
}

// ---------------------------------------------------------------------------
// Elementwise fp32 -> bf16 hi/lo split
// ---------------------------------------------------------------------------
__global__ void split_kernel(const float* __restrict__ src,
                             __nv_bfloat16* __restrict__ dh,
                             __nv_bfloat16* __restrict__ dl, int n4) {
    int i = blockIdx.x * blockDim.x + threadIdx.x;
    int stride = gridDim.x * blockDim.x;
    for (; i < n4; i += stride) {
        float4 v = ((const float4*)src)[i];
        __nv_bfloat162 h01 = __floats2bfloat162_rn(v.x, v.y);
        __nv_bfloat162 h23 = __floats2bfloat162_rn(v.z, v.w);
        __nv_bfloat162 l01 = __floats2bfloat162_rn(v.x - __bfloat162float(h01.x),
                                                   v.y - __bfloat162float(h01.y));
        __nv_bfloat162 l23 = __floats2bfloat162_rn(v.z - __bfloat162float(h23.x),
                                                   v.w - __bfloat162float(h23.y));
        ((uint2*)dh)[i] = make_uint2(b2u(h01), b2u(h23));
        ((uint2*)dl)[i] = make_uint2(b2u(l01), b2u(l23));
    }
}

// Elementwise fp32 -> fp16 hi/lo split
__global__ void split_kernel_h(const float* __restrict__ src,
                               __half* __restrict__ dh,
                               __half* __restrict__ dl, int n4) {
    int i = blockIdx.x * blockDim.x + threadIdx.x;
    int stride = gridDim.x * blockDim.x;
    for (; i < n4; i += stride) {
        float4 v = ((const float4*)src)[i];
        __half2 h01 = __floats2half2_rn(v.x, v.y);
        __half2 h23 = __floats2half2_rn(v.z, v.w);
        float2 f01 = __half22float2(h01);
        float2 f23 = __half22float2(h23);
        __half2 l01 = __floats2half2_rn(v.x - f01.x, v.y - f01.y);
        __half2 l23 = __floats2half2_rn(v.z - f23.x, v.w - f23.y);
        ((uint2*)dh)[i] = make_uint2(h2u(h01), h2u(h23));
        ((uint2*)dl)[i] = make_uint2(h2u(l01), h2u(l23));
    }
}

// ---------------------------------------------------------------------------
// Split-bf16 NT GEMM (QKV; R7-verified config): cp.async double-buffer,
// ldmatrix, 2 CTAs/SM. 128x128 tile, K-chunk 32, 8 warps 4x2, 80B rows.
// Epilogue: Q/K fp16 single + V fp16 hi/lo transposed.
// ---------------------------------------------------------------------------
#define APAD_B 80
#define TILE_B (128 * APAD_B)              // 10240
#define BUF_B  (4 * TILE_B)                // AH, AL, BH, BL = 40960
#define GEMM_SMEM (2 * BUF_B)              // 81920
#define NCHUNK (CC / 32)                   // 32

__global__ __launch_bounds__(256, 2) void qkv_gemm(
    const __nv_bfloat16* __restrict__ AH, const __nv_bfloat16* __restrict__ AL,
    const __nv_bfloat16* __restrict__ BH, const __nv_bfloat16* __restrict__ BL) {
    extern __shared__ char smc[];
    const uint32_t smb = smem_u32(smc);
    const int tid = threadIdx.x;
    const int m0 = blockIdx.y * 128;
    const int n0 = blockIdx.x * 128;
    const int wid = tid >> 5;
    const int lane = tid & 31;
    const int gid = lane >> 2;
    const int tig = lane & 3;
    const int wm = wid & 3;
    const int wn = wid >> 2;

    const uint32_t laneA = (uint32_t)(((lane & 7) + ((lane >> 3) & 1) * 8) * APAD_B
                                      + (lane >> 4) * 16);
    const uint32_t laneB = (uint32_t)(((lane & 7) + ((lane >> 4) & 1) * 8) * APAD_B
                                      + ((lane >> 3) & 1) * 16);

    float acc[2][8][4];
#pragma unroll
    for (int i = 0; i < 2; i++)
#pragma unroll
        for (int j = 0; j < 8; j++)
#pragma unroll
            for (int q = 0; q < 4; q++) acc[i][j][q] = 0.f;

    auto copyc = [&](int kk, int bufi) {
        uint32_t bbase = smb + bufi * BUF_B;
#pragma unroll
        for (int l = 0; l < 8; l++) {
            const int tile = l >> 1;
            int e2 = (l & 1) * 256 + tid;
            int r = e2 >> 2;
            int q = e2 & 3;
            const __nv_bfloat16* src =
                (tile == 0) ? AH : (tile == 1) ? AL : (tile == 2) ? BH : BL;
            int row = (tile < 2 ? m0 : n0) + r;
            cpa16(bbase + tile * TILE_B + r * APAD_B + q * 16,
                  src + (size_t)row * CC + kk + q * 8);
        }
    };

    auto compute = [&](uint32_t bufu) {
#pragma unroll
        for (int ks = 0; ks < 2; ks++) {
            uint32_t ah[2][4], al[2][4];
#pragma unroll
            for (int i = 0; i < 2; i++) {
                uint32_t aaddr = bufu + laneA + (wm * 32 + i * 16) * APAD_B + ks * 32;
                LDSM4(ah[i], aaddr);
                LDSM4(al[i], aaddr + TILE_B);
            }
#pragma unroll
            for (int jp = 0; jp < 4; jp++) {
                uint32_t baddr = bufu + 2 * TILE_B + laneB
                               + (wn * 64 + jp * 16) * APAD_B + ks * 32;
                uint32_t rh[4], rl[4];
                LDSM4(rh, baddr);
                LDSM4(rl, baddr + TILE_B);
#pragma unroll
                for (int t = 0; t < 2; t++) {
                    int j = 2 * jp + t;
#pragma unroll
                    for (int i = 0; i < 2; i++) {
                        mma16816(acc[i][j], ah[i], rh[2 * t], rh[2 * t + 1]);
                        mma16816(acc[i][j], ah[i], rl[2 * t], rl[2 * t + 1]);
                        mma16816(acc[i][j], al[i], rh[2 * t], rh[2 * t + 1]);
                    }
                }
            }
        }
    };

    copyc(0, 0);
    CP_COMMIT();
    for (int c = 0; c < NCHUNK; c++) {
        if (c + 1 < NCHUNK) {
            copyc((c + 1) * 32, (c + 1) & 1);
            CP_COMMIT();
            CP_WAIT1();
        } else {
            CP_WAIT0();
        }
        __syncthreads();
        compute(smb + (uint32_t)(c & 1) * BUF_B);
        __syncthreads();
    }

    // ---- epilogue: fragments -> smem staging
    float* Ds = (float*)smc;               // 128 x 132 f32 = 67584 <= 81920
#pragma unroll
    for (int i = 0; i < 2; i++) {
        int rr = wm * 32 + i * 16 + gid;
#pragma unroll
        for (int j = 0; j < 8; j++) {
            int cc = wn * 64 + j * 8 + tig * 2;
            *(float2*)&Ds[rr * 132 + cc]       = make_float2(acc[i][j][0], acc[i][j][1]);
            *(float2*)&Ds[(rr + 8) * 132 + cc] = make_float2(acc[i][j][2], acc[i][j][3]);
        }
    }
    __syncthreads();

    // two 64-wide segments; each wholly one of q/k/v (192 % 64 == 0)
#pragma unroll
    for (int seg = 0; seg < 2; seg++) {
        int gn0 = n0 + seg * 64;
        int h = gn0 / 192;
        int part = (gn0 % 192) >> 6;
        if (part < 2) {
            __half* dst = (part == 0) ? g_qf : g_kf;       // fp16, single
#pragma unroll
            for (int it = 0; it < 16; it++) {
                int m = it * 8 + (tid >> 5);
                int d2 = (tid & 31) * 2;
                float v0 = Ds[m * 132 + seg * 64 + d2];
                float v1 = Ds[m * 132 + seg * 64 + d2 + 1];
                __half2 hp = __floats2half2_rn(v0, v1);
                int gm = m0 + m; int b = gm >> 11; int t = gm & 2047;
                size_t idx = (((size_t)(b * HH + h)) * TT + t) * HD + d2;
                *(uint32_t*)(dst + idx) = h2u(hp);
            }
        } else {                            // V: transposed [bh][d][t], fp16 hi/lo
#pragma unroll
            for (int it = 0; it < 16; it++) {
                int flat = it * 256 + tid;         // 0..4095
                int d = flat >> 6;                 // 0..63
                int tp = (flat & 63) * 2;          // pair along t
                float v0 = Ds[tp * 132 + seg * 64 + d];
                float v1 = Ds[(tp + 1) * 132 + seg * 64 + d];
                __half2 hp = __floats2half2_rn(v0, v1);
                float2 hf = __half22float2(hp);
                __half2 lp = __floats2half2_rn(v0 - hf.x, v1 - hf.y);
                int gm = m0 + tp; int b = gm >> 11; int t = gm & 2047;
                size_t idx = (((size_t)(b * HH + h)) * HD + d) * TT + t;
                *(uint32_t*)(g_vf + idx) = h2u(hp);
                *(uint32_t*)(g_vl + idx) = h2u(lp);
            }
        }
    }
}

// ---------------------------------------------------------------------------
// Proj GEMM: A = att-out fp16 single, W = fp16 hi/lo split (2 products).
// Same pipeline skeleton; 3 smem tiles per buffer.
// ---------------------------------------------------------------------------
#define PBUF_B (3 * TILE_B)                // AF, WH, WL = 30720
#define PROJ_SMEM (128 * 132 * 4)          // 67584 (epilogue staging dominates)

__global__ __launch_bounds__(256, 2) void proj_gemm(
    const __half* __restrict__ AF,
    const __half* __restrict__ WH, const __half* __restrict__ WL,
    const float* __restrict__ bias, float* __restrict__ out) {
    extern __shared__ char smc[];
    const uint32_t smb = smem_u32(smc);
    const int tid = threadIdx.x;
    const int m0 = blockIdx.y * 128;
    const int n0 = blockIdx.x * 128;
    const int wid = tid >> 5;
    const int lane = tid & 31;
    const int gid = lane >> 2;
    const int tig = lane & 3;
    const int wm = wid & 3;
    const int wn = wid >> 2;

    const uint32_t laneA = (uint32_t)(((lane & 7) + ((lane >> 3) & 1) * 8) * APAD_B
                                      + (lane >> 4) * 16);
    const uint32_t laneB = (uint32_t)(((lane & 7) + ((lane >> 4) & 1) * 8) * APAD_B
                                      + ((lane >> 3) & 1) * 16);

    float acc[2][8][4];
#pragma unroll
    for (int i = 0; i < 2; i++)
#pragma unroll
        for (int j = 0; j < 8; j++)
#pragma unroll
            for (int q = 0; q < 4; q++) acc[i][j][q] = 0.f;

    auto copyc = [&](int kk, int bufi) {
        uint32_t bbase = smb + bufi * PBUF_B;
#pragma unroll
        for (int l = 0; l < 6; l++) {
            const int tile = l >> 1;               // 0=AF, 1=WH, 2=WL
            int e2 = (l & 1) * 256 + tid;
            int r = e2 >> 2;
            int q = e2 & 3;
            const __half* src = (tile == 0) ? AF : (tile == 1) ? WH : WL;
            int row = (tile == 0 ? m0 : n0) + r;
            cpa16(bbase + tile * TILE_B + r * APAD_B + q * 16,
                  src + (size_t)row * CC + kk + q * 8);
        }
    };

    auto compute = [&](uint32_t bufu) {
#pragma unroll
        for (int ks = 0; ks < 2; ks++) {
            uint32_t af[2][4];
#pragma unroll
            for (int i = 0; i < 2; i++) {
                uint32_t aaddr = bufu + laneA + (wm * 32 + i * 16) * APAD_B + ks * 32;
                LDSM4(af[i], aaddr);
            }
#pragma unroll
            for (int jp = 0; jp < 4; jp++) {
                uint32_t baddr = bufu + TILE_B + laneB
                               + (wn * 64 + jp * 16) * APAD_B + ks * 32;
                uint32_t rh[4], rl[4];
                LDSM4(rh, baddr);
                LDSM4(rl, baddr + TILE_B);
#pragma unroll
                for (int t = 0; t < 2; t++) {
                    int j = 2 * jp + t;
#pragma unroll
                    for (int i = 0; i < 2; i++) {
                        mma16816h(acc[i][j], af[i], rh[2 * t], rh[2 * t + 1]);
                        mma16816h(acc[i][j], af[i], rl[2 * t], rl[2 * t + 1]);
                    }
                }
            }
        }
    };

    copyc(0, 0);
    CP_COMMIT();
    for (int c = 0; c < NCHUNK; c++) {
        if (c + 1 < NCHUNK) {
            copyc((c + 1) * 32, (c + 1) & 1);
            CP_COMMIT();
            CP_WAIT1();
        } else {
            CP_WAIT0();
        }
        __syncthreads();
        compute(smb + (uint32_t)(c & 1) * PBUF_B);
        __syncthreads();
    }

    float* Ds = (float*)smc;
#pragma unroll
    for (int i = 0; i < 2; i++) {
        int rr = wm * 32 + i * 16 + gid;
#pragma unroll
        for (int j = 0; j < 8; j++) {
            int cc = wn * 64 + j * 8 + tig * 2;
            *(float2*)&Ds[rr * 132 + cc]       = make_float2(acc[i][j][0], acc[i][j][1]);
            *(float2*)&Ds[(rr + 8) * 132 + cc] = make_float2(acc[i][j][2], acc[i][j][3]);
        }
    }
    __syncthreads();

#pragma unroll 4
    for (int ll = 0; ll < 64; ll++) {
        int flat = ll * 256 + tid;
        int n = flat & 127;
        int m = flat >> 7;
        out[(size_t)(m0 + m) * CC + n0 + n] = Ds[m * 132 + n] + bias[n0 + n];
    }
}

// ---------------------------------------------------------------------------
// Flash attention. S = Q K^T single fp16 MMA; PV = pf*(vh + vl), 2 fp16 MMAs.
// BM=128 (8 warps x 16 rows), BN=64, 2 CTAs/SM, base-2 softmax, heavy-first.
// Smem per buffer: Kf + Vh + Vl (all fp16), rows padded to 144B.
// ---------------------------------------------------------------------------
#define AT_ROW 144
#define AT_TILE (64 * AT_ROW)              // 9216
#define AT_BUF (3 * AT_TILE)               // 27648
#define ATT_SMEM_BYTES (2 * AT_BUF)        // 55296
#define SCL2 0.1803368801111137f           // 0.125 * log2(e)

__global__ __launch_bounds__(256, 2) void attn_kernel() {
    extern __shared__ char smc[];
    const uint32_t smb = smem_u32(smc);
    const int tid = threadIdx.x;
    const int bh = blockIdx.y;
    const int q0 = (gridDim.x - 1 - blockIdx.x) * 128;   // heavy tiles first
    const int wid = tid >> 5;
    const int lane = tid & 31;
    const int gid = lane >> 2;
    const int tig = lane & 3;
    const int r0 = q0 + wid * 16 + gid;

    const __half* Qf = g_qf + (size_t)bh * TT * HD;
    const __half* Kf = g_kf + (size_t)bh * TT * HD;
    const __half* Vf = g_vf + (size_t)bh * HD * TT;
    const __half* Vl = g_vl + (size_t)bh * HD * TT;

    const uint32_t laneB = (uint32_t)(((lane & 7) + ((lane >> 4) & 1) * 8) * AT_ROW
                                      + ((lane >> 3) & 1) * 16);

    // ---- Q fragments (fp16, single), direct ldg
    uint32_t qf[4][4];
#pragma unroll
    for (int ks = 0; ks < 4; ks++)
#pragma unroll
        for (int hv = 0; hv < 2; hv++)
#pragma unroll
            for (int rr = 0; rr < 2; rr++) {
                size_t o = (size_t)(r0 + rr * 8) * HD + ks * 16 + hv * 8 + tig * 2;
                qf[ks][hv * 2 + rr] = *(const uint32_t*)(Qf + o);
            }

    float oacc[8][4];
#pragma unroll
    for (int j = 0; j < 8; j++)
#pragma unroll
        for (int q = 0; q < 4; q++) oacc[j][q] = 0.f;
    float mr0 = -1e30f, mr1 = -1e30f, lr0 = 0.f, lr1 = 0.f;

    auto copyc = [&](int c, int bufi) {
        const int k0 = c * 64;
        uint32_t bbase = smb + bufi * AT_BUF;
#pragma unroll
        for (int l = 0; l < 6; l++) {
            const int tile = l >> 1;            // 0=Kf, 1=Vf, 2=Vl
            int e2 = (l & 1) * 256 + tid;       // 0..511
            int r = e2 >> 3;                    // 0..63
            int q = e2 & 7;                     // 0..7
            const void* src;
            if (tile == 0)      src = Kf + (size_t)(k0 + r) * HD + q * 8;
            else if (tile == 1) src = Vf + (size_t)r * TT + k0 + q * 8;
            else                src = Vl + (size_t)r * TT + k0 + q * 8;
            cpa16(bbase + tile * AT_TILE + r * AT_ROW + q * 16, src);
        }
    };

    const int jmax = (q0 >> 6) + 2;
    copyc(0, 0);
    CP_COMMIT();
    for (int c = 0; c < jmax; c++) {
        if (c + 1 < jmax) {
            copyc(c + 1, (c + 1) & 1);
            CP_COMMIT();
            CP_WAIT1();
        } else {
            CP_WAIT0();
        }
        __syncthreads();
        const uint32_t KT = smb + (uint32_t)(c & 1) * AT_BUF;
        const uint32_t VT = KT + AT_TILE;

        // ---- S = Q K^T, single fp16 product
        float s[8][4];
#pragma unroll
        for (int j = 0; j < 8; j++)
#pragma unroll
            for (int q = 0; q < 4; q++) s[j][q] = 0.f;
#pragma unroll
        for (int ks = 0; ks < 4; ks++) {
#pragma unroll
            for (int jp = 0; jp < 4; jp++) {
                uint32_t kaddr = KT + laneB + jp * 16 * AT_ROW + ks * 32;
                uint32_t rk[4];
                LDSM4(rk, kaddr);
#pragma unroll
                for (int t = 0; t < 2; t++) {
                    int j = 2 * jp + t;
                    mma16816h(s[j], qf[ks], rk[2 * t], rk[2 * t + 1]);
                }
            }
        }

        // scale into base-2 logit domain
        const int k0 = c * 64;
#pragma unroll
        for (int j = 0; j < 8; j++)
#pragma unroll
            for (int q = 0; q < 4; q++) s[j][q] *= SCL2;
        if (c >= jmax - 2) {
#pragma unroll
            for (int j = 0; j < 8; j++) {
                int col = k0 + 8 * j + 2 * tig;
                if (col > r0)          s[j][0] = -1e30f;
                if (col + 1 > r0)      s[j][1] = -1e30f;
                if (col > r0 + 8)      s[j][2] = -1e30f;
                if (col + 1 > r0 + 8)  s[j][3] = -1e30f;
            }
        }

        // ---- online softmax (base-2)
        float pm0 = -1e30f, pm1 = -1e30f;
#pragma unroll
        for (int j = 0; j < 8; j++) {
            pm0 = fmaxf(pm0, fmaxf(s[j][0], s[j][1]));
            pm1 = fmaxf(pm1, fmaxf(s[j][2], s[j][3]));
        }
        pm0 = fmaxf(pm0, __shfl_xor_sync(0xffffffffu, pm0, 1));
        pm0 = fmaxf(pm0, __shfl_xor_sync(0xffffffffu, pm0, 2));
        pm1 = fmaxf(pm1, __shfl_xor_sync(0xffffffffu, pm1, 1));
        pm1 = fmaxf(pm1, __shfl_xor_sync(0xffffffffu, pm1, 2));
        float mn0 = fmaxf(mr0, pm0), mn1 = fmaxf(mr1, pm1);
        float a0 = ex2f(mr0 - mn0), a1 = ex2f(mr1 - mn1);
        float sum0 = 0.f, sum1 = 0.f;
#pragma unroll
        for (int j = 0; j < 8; j++) {
            s[j][0] = ex2f(s[j][0] - mn0);
            s[j][1] = ex2f(s[j][1] - mn0);
            s[j][2] = ex2f(s[j][2] - mn1);
            s[j][3] = ex2f(s[j][3] - mn1);
            sum0 += s[j][0] + s[j][1];
            sum1 += s[j][2] + s[j][3];
        }
        sum0 += __shfl_xor_sync(0xffffffffu, sum0, 1);
        sum0 += __shfl_xor_sync(0xffffffffu, sum0, 2);
        sum1 += __shfl_xor_sync(0xffffffffu, sum1, 1);
        sum1 += __shfl_xor_sync(0xffffffffu, sum1, 2);
        lr0 = lr0 * a0 + sum0;
        lr1 = lr1 * a1 + sum1;
        mr0 = mn0; mr1 = mn1;
#pragma unroll
        for (int j = 0; j < 8; j++) {
            oacc[j][0] *= a0; oacc[j][1] *= a0;
            oacc[j][2] *= a1; oacc[j][3] *= a1;
        }

        // ---- O += P V (pf * vh + pf * vl), P single fp16, packed per-ks
#pragma unroll
        for (int ks = 0; ks < 4; ks++) {
            uint32_t pf[4];
            int j0 = 2 * ks, j1 = 2 * ks + 1;
#pragma unroll
            for (int part = 0; part < 4; part++) {
                int jj = (part < 2) ? j0 : j1;
                int qa = (part & 1) * 2;
                pf[part] = h2u(__floats2half2_rn(s[jj][qa], s[jj][qa + 1]));
            }
#pragma unroll
            for (int jp = 0; jp < 4; jp++) {
                uint32_t vaddr = VT + laneB + jp * 16 * AT_ROW + ks * 32;
                uint32_t rh[4], rl[4];
                LDSM4(rh, vaddr);
                LDSM4(rl, vaddr + AT_TILE);
#pragma unroll
                for (int t = 0; t < 2; t++) {
                    int j = 2 * jp + t;
                    mma16816h(oacc[j], pf, rh[2 * t], rh[2 * t + 1]);
                    mma16816h(oacc[j], pf, rl[2 * t], rl[2 * t + 1]);
                }
            }
        }
        __syncthreads();
    }

    // ---- epilogue: normalize, write g_af (fp16 single) [B,T,C]
    const int b = bh >> 4;
    const int h = bh & 15;
    float inv0 = 1.f / lr0, inv1 = 1.f / lr1;
#pragma unroll
    for (int j = 0; j < 8; j++) {
        int d = 8 * j + 2 * tig;
        size_t o0 = ((size_t)(b * TT + r0)) * CC + h * HD + d;
        size_t o1 = ((size_t)(b * TT + r0 + 8)) * CC + h * HD + d;
        *(uint32_t*)(g_af + o0) =
            h2u(__floats2half2_rn(oacc[j][0] * inv0, oacc[j][1] * inv0));
        *(uint32_t*)(g_af + o1) =
            h2u(__floats2half2_rn(oacc[j][2] * inv1, oacc[j][3] * inv1));
    }
}

// ---------------------------------------------------------------------------

extern "C" void kernel_launch(void* const* d_in, const int* in_sizes, int n_in,
                              void* d_out, int out_size) {
    const float* x      = (const float*)d_in[0];
    const float* w_qkv  = (const float*)d_in[1];
    const float* w_proj = (const float*)d_in[2];
    const float* b_proj = (const float*)d_in[3];
    float* out = (float*)d_out;

    __nv_bfloat16 *xh, *xl, *wqh, *wql;
    __half *wpf, *wpl, *af;
    cudaGetSymbolAddress((void**)&xh,  g_xh);
    cudaGetSymbolAddress((void**)&xl,  g_xl);
    cudaGetSymbolAddress((void**)&wqh, g_wqh);
    cudaGetSymbolAddress((void**)&wql, g_wql);
    cudaGetSymbolAddress((void**)&wpf, g_wpf);
    cudaGetSymbolAddress((void**)&wpl, g_wpl);
    cudaGetSymbolAddress((void**)&af,  g_af);

    cudaFuncSetAttribute(qkv_gemm, cudaFuncAttributeMaxDynamicSharedMemorySize, GEMM_SMEM);
    cudaFuncSetAttribute(proj_gemm, cudaFuncAttributeMaxDynamicSharedMemorySize, PROJ_SMEM);
    cudaFuncSetAttribute(attn_kernel, cudaFuncAttributeMaxDynamicSharedMemorySize, ATT_SMEM_BYTES);

    split_kernel<<<2048, 256>>>(x, xh, xl, MROWS * CC / 4);
    split_kernel<<<2048, 256>>>(w_qkv, wqh, wql, N_QKV * CC / 4);
    split_kernel_h<<<1024, 256>>>(w_proj, wpf, wpl, CC * CC / 4);

    qkv_gemm<<<dim3(N_QKV / 128, MROWS / 128), 256, GEMM_SMEM>>>(xh, xl, wqh, wql);
    attn_kernel<<<dim3(TT / 128, BB * HH), 256, ATT_SMEM_BYTES>>>();
    proj_gemm<<<dim3(CC / 128, MROWS / 128), 256, PROJ_SMEM>>>(af, wpf, wpl, b_proj, out);
}

// round 14
// speedup vs baseline: 2.2368x; 1.1962x over previous
#include <cuda_runtime.h>
#include <cuda_bf16.h>
#include <cuda_fp16.h>
#include <math.h>
#include <stdint.h>

// Problem constants
#define BB 4
#define TT 2048
#define CC 1024
#define HH 16
#define HD 64
#define MROWS (BB * TT)          // 8192
#define N_QKV (3 * CC)           // 3072

// ---------------------------------------------------------------------------
// Global scratch (allocation-free)
// ---------------------------------------------------------------------------
__device__ __half g_xf[MROWS * CC];                                  // x fp16 single
__device__ __half g_wqf[N_QKV * CC], g_wql[N_QKV * CC];              // w_qkv fp16 hi/lo
__device__ __half g_wpf[CC * CC],    g_wpl[CC * CC];                 // w_proj fp16 hi/lo
__device__ __half g_qf[BB * HH * TT * HD];                           // [bh][t][d] fp16
__device__ __half g_kf[BB * HH * TT * HD];                           // [bh][t][d] fp16
__device__ __half g_vf[BB * HH * TT * HD], g_vl[BB * HH * TT * HD];  // [bh][d][t] fp16 hi/lo
__device__ __half g_af[MROWS * CC];                                  // att out [B,T,C] fp16

// ---------------------------------------------------------------------------
// Helpers
// ---------------------------------------------------------------------------
__device__ __forceinline__ uint32_t h2u(__half2 h) {
    return *reinterpret_cast<uint32_t*>(&h);
}
__device__ __forceinline__ uint32_t smem_u32(const void* p) {
    uint32_t a;
    asm("{ .reg .u64 t; cvta.to.shared.u64 t, %1; cvt.u32.u64 %0, t; }"
        : "=r"(a) : "l"(p));
    return a;
}
__device__ __forceinline__ void cpa16(uint32_t dst, const void* src) {
    asm volatile("cp.async.cg.shared.global [%0], [%1], 16;"
                 :: "r"(dst), "l"(src) : "memory");
}
#define CP_COMMIT() asm volatile("cp.async.commit_group;" ::: "memory")
#define CP_WAIT0()  asm volatile("cp.async.wait_group 0;" ::: "memory")
#define CP_WAIT1()  asm volatile("cp.async.wait_group 1;" ::: "memory")

#define LDSM4(r, addr) \
    asm volatile("ldmatrix.sync.aligned.m8n8.x4.shared.b16 {%0,%1,%2,%3}, [%4];" \
        : "=r"((r)[0]), "=r"((r)[1]), "=r"((r)[2]), "=r"((r)[3]) : "r"(addr))

__device__ __forceinline__ float ex2f(float x) {
    float r;
    asm("ex2.approx.f32 %0, %1;" : "=f"(r) : "f"(x));
    return r;
}

__device__ __forceinline__ void mma16816h(float* c, const uint32_t* a,
                                          uint32_t b0, uint32_t b1) {
    asm volatile(
        "mma.sync.aligned.m16n8k16.row.col.f32.f16.f16.f32 "
        "{%0,%1,%2,%3}, {%4,%5,%6,%7}, {%8,%9}, {%0,%1,%2,%3};"
        : "+f"(c[0]), "+f"(c[1]), "+f"(c[2]), "+f"(c[3])
        : "r"(a[0]), "r"(a[1]), "r"(a[2]), "r"(a[3]), "r"(b0), "r"(b1));
}

// ---------------------------------------------------------------------------
// Elementwise pre-passes
// ---------------------------------------------------------------------------
__global__ void tofp16_kernel(const float* __restrict__ src,
                              __half* __restrict__ d, int n4) {
    int i = blockIdx.x * blockDim.x + threadIdx.x;
    int stride = gridDim.x * blockDim.x;
    for (; i < n4; i += stride) {
        float4 v = ((const float4*)src)[i];
        ((uint2*)d)[i] = make_uint2(h2u(__floats2half2_rn(v.x, v.y)),
                                    h2u(__floats2half2_rn(v.z, v.w)));
    }
}

__global__ void split_kernel_h(const float* __restrict__ src,
                               __half* __restrict__ dh,
                               __half* __restrict__ dl, int n4) {
    int i = blockIdx.x * blockDim.x + threadIdx.x;
    int stride = gridDim.x * blockDim.x;
    for (; i < n4; i += stride) {
        float4 v = ((const float4*)src)[i];
        __half2 h01 = __floats2half2_rn(v.x, v.y);
        __half2 h23 = __floats2half2_rn(v.z, v.w);
        float2 f01 = __half22float2(h01);
        float2 f23 = __half22float2(h23);
        __half2 l01 = __floats2half2_rn(v.x - f01.x, v.y - f01.y);
        __half2 l23 = __floats2half2_rn(v.z - f23.x, v.w - f23.y);
        ((uint2*)dh)[i] = make_uint2(h2u(h01), h2u(h23));
        ((uint2*)dl)[i] = make_uint2(h2u(l01), h2u(l23));
    }
}

// ---------------------------------------------------------------------------
// 2-product fp16 NT GEMM skeleton (A fp16 single, B fp16 hi/lo):
// cp.async double-buffer, ldmatrix, 2 CTAs/SM. 128x128 tile, K-chunk 32,
// 8 warps 4x2, smem rows padded to 80B (LDSM conflict-free).
// qkv_gemm: epilogue writes Q/K fp16 + V fp16 hi/lo transposed.
// proj_gemm: epilogue writes out = C + bias (fp32).
// ---------------------------------------------------------------------------
#define APAD_B 80
#define TILE_B (128 * APAD_B)              // 10240
#define PBUF_B (3 * TILE_B)                // AF, BH, BL = 30720
#define GSMEM  (128 * 132 * 4)             // 67584 >= 2*PBUF_B, covers Ds
#define NCHUNK (CC / 32)                   // 32

// Shared mainloop body (identical for both GEMMs)
#define GEMM_MAINLOOP(AF, BH, BL)                                              \
    const uint32_t smb = smem_u32(smc);                                        \
    const int tid = threadIdx.x;                                               \
    const int m0 = blockIdx.y * 128;                                           \
    const int n0 = blockIdx.x * 128;                                           \
    const int wid = tid >> 5;                                                  \
    const int lane = tid & 31;                                                 \
    const int gid = lane >> 2;                                                 \
    const int tig = lane & 3;                                                  \
    const int wm = wid & 3;                                                    \
    const int wn = wid >> 2;                                                   \
    const uint32_t laneA = (uint32_t)(((lane & 7) + ((lane >> 3) & 1) * 8)     \
                                      * APAD_B + (lane >> 4) * 16);            \
    const uint32_t laneB = (uint32_t)(((lane & 7) + ((lane >> 4) & 1) * 8)     \
                                      * APAD_B + ((lane >> 3) & 1) * 16);      \
    float acc[2][8][4];                                                        \
    _Pragma("unroll")                                                          \
    for (int i = 0; i < 2; i++)                                                \
        _Pragma("unroll")                                                      \
        for (int j = 0; j < 8; j++)                                            \
            _Pragma("unroll")                                                  \
            for (int q = 0; q < 4; q++) acc[i][j][q] = 0.f;                    \
    auto copyc = [&](int kk, int bufi) {                                       \
        uint32_t bbase = smb + bufi * PBUF_B;                                  \
        _Pragma("unroll")                                                      \
        for (int l = 0; l < 6; l++) {                                          \
            const int tile = l >> 1;                                           \
            int e2 = (l & 1) * 256 + tid;                                      \
            int r = e2 >> 2;                                                   \
            int q = e2 & 3;                                                    \
            const __half* src = (tile == 0) ? AF : (tile == 1) ? BH : BL;      \
            int row = (tile == 0 ? m0 : n0) + r;                               \
            cpa16(bbase + tile * TILE_B + r * APAD_B + q * 16,                 \
                  src + (size_t)row * CC + kk + q * 8);                        \
        }                                                                      \
    };                                                                         \
    auto compute = [&](uint32_t bufu) {                                        \
        _Pragma("unroll")                                                      \
        for (int ks = 0; ks < 2; ks++) {                                       \
            uint32_t af[2][4];                                                 \
            _Pragma("unroll")                                                  \
            for (int i = 0; i < 2; i++) {                                      \
                uint32_t aaddr = bufu + laneA + (wm * 32 + i * 16) * APAD_B    \
                               + ks * 32;                                      \
                LDSM4(af[i], aaddr);                                           \
            }                                                                  \
            _Pragma("unroll")                                                  \
            for (int jp = 0; jp < 4; jp++) {                                   \
                uint32_t baddr = bufu + TILE_B + laneB                         \
                               + (wn * 64 + jp * 16) * APAD_B + ks * 32;       \
                uint32_t rh[4], rl[4];                                         \
                LDSM4(rh, baddr);                                              \
                LDSM4(rl, baddr + TILE_B);                                     \
                _Pragma("unroll")                                              \
                for (int t = 0; t < 2; t++) {                                  \
                    int j = 2 * jp + t;                                        \
                    _Pragma("unroll")                                          \
                    for (int i = 0; i < 2; i++) {                              \
                        mma16816h(acc[i][j], af[i], rh[2 * t], rh[2 * t + 1]); \
                        mma16816h(acc[i][j], af[i], rl[2 * t], rl[2 * t + 1]); \
                    }                                                          \
                }                                                              \
            }                                                                  \
        }                                                                      \
    };                                                                         \
    copyc(0, 0);                                                               \
    CP_COMMIT();                                                               \
    for (int c = 0; c < NCHUNK; c++) {                                         \
        if (c + 1 < NCHUNK) {                                                  \
            copyc((c + 1) * 32, (c + 1) & 1);                                  \
            CP_COMMIT();                                                       \
            CP_WAIT1();                                                        \
        } else {                                                               \
            CP_WAIT0();                                                        \
        }                                                                      \
        __syncthreads();                                                       \
        compute(smb + (uint32_t)(c & 1) * PBUF_B);                             \
        __syncthreads();                                                       \
    }                                                                          \
    float* Ds = (float*)smc;                                                   \
    _Pragma("unroll")                                                          \
    for (int i = 0; i < 2; i++) {                                              \
        int rr = wm * 32 + i * 16 + gid;                                       \
        _Pragma("unroll")                                                      \
        for (int j = 0; j < 8; j++) {                                          \
            int cc = wn * 64 + j * 8 + tig * 2;                                \
            *(float2*)&Ds[rr * 132 + cc] =                                     \
                make_float2(acc[i][j][0], acc[i][j][1]);                       \
            *(float2*)&Ds[(rr + 8) * 132 + cc] =                               \
                make_float2(acc[i][j][2], acc[i][j][3]);                       \
        }                                                                      \
    }                                                                          \
    __syncthreads();

__global__ __launch_bounds__(256, 2) void qkv_gemm(
    const __half* __restrict__ AF,
    const __half* __restrict__ WH, const __half* __restrict__ WL) {
    extern __shared__ char smc[];
    GEMM_MAINLOOP(AF, WH, WL)

    // two 64-wide segments; each wholly one of q/k/v (192 % 64 == 0)
#pragma unroll
    for (int seg = 0; seg < 2; seg++) {
        int gn0 = n0 + seg * 64;
        int h = gn0 / 192;
        int part = (gn0 % 192) >> 6;
        if (part < 2) {
            __half* dst = (part == 0) ? g_qf : g_kf;       // fp16, single
#pragma unroll
            for (int it = 0; it < 16; it++) {
                int m = it * 8 + (tid >> 5);
                int d2 = (tid & 31) * 2;
                float v0 = Ds[m * 132 + seg * 64 + d2];
                float v1 = Ds[m * 132 + seg * 64 + d2 + 1];
                __half2 hp = __floats2half2_rn(v0, v1);
                int gm = m0 + m; int b = gm >> 11; int t = gm & 2047;
                size_t idx = (((size_t)(b * HH + h)) * TT + t) * HD + d2;
                *(uint32_t*)(dst + idx) = h2u(hp);
            }
        } else {                            // V: transposed [bh][d][t], fp16 hi/lo
#pragma unroll
            for (int it = 0; it < 16; it++) {
                int flat = it * 256 + tid;         // 0..4095
                int d = flat >> 6;                 // 0..63
                int tp = (flat & 63) * 2;          // pair along t
                float v0 = Ds[tp * 132 + seg * 64 + d];
                float v1 = Ds[(tp + 1) * 132 + seg * 64 + d];
                __half2 hp = __floats2half2_rn(v0, v1);
                float2 hf = __half22float2(hp);
                __half2 lp = __floats2half2_rn(v0 - hf.x, v1 - hf.y);
                int gm = m0 + tp; int b = gm >> 11; int t = gm & 2047;
                size_t idx = (((size_t)(b * HH + h)) * HD + d) * TT + t;
                *(uint32_t*)(g_vf + idx) = h2u(hp);
                *(uint32_t*)(g_vl + idx) = h2u(lp);
            }
        }
    }
}

__global__ __launch_bounds__(256, 2) void proj_gemm(
    const __half* __restrict__ AF,
    const __half* __restrict__ WH, const __half* __restrict__ WL,
    const float* __restrict__ bias, float* __restrict__ out) {
    extern __shared__ char smc[];
    GEMM_MAINLOOP(AF, WH, WL)

#pragma unroll 4
    for (int ll = 0; ll < 64; ll++) {
        int flat = ll * 256 + tid;
        int n = flat & 127;
        int m = flat >> 7;
        out[(size_t)(m0 + m) * CC + n0 + n] = Ds[m * 132 + n] + bias[n0 + n];
    }
}

// ---------------------------------------------------------------------------
// Flash attention. S = Q K^T single fp16 MMA; PV = pf*(vh + vl), 2 fp16 MMAs.
// BM=128 (8 warps x 16 rows), BN=64, 2 CTAs/SM, base-2 softmax, heavy-first.
// Smem per buffer: Kf + Vf + Vl (all fp16), rows padded to 144B.
// ---------------------------------------------------------------------------
#define AT_ROW 144
#define AT_TILE (64 * AT_ROW)              // 9216
#define AT_BUF (3 * AT_TILE)               // 27648
#define ATT_SMEM_BYTES (2 * AT_BUF)        // 55296
#define SCL2 0.1803368801111137f           // 0.125 * log2(e)

__global__ __launch_bounds__(256, 2) void attn_kernel() {
    extern __shared__ char smc[];
    const uint32_t smb = smem_u32(smc);
    const int tid = threadIdx.x;
    const int bh = blockIdx.y;
    const int q0 = (gridDim.x - 1 - blockIdx.x) * 128;   // heavy tiles first
    const int wid = tid >> 5;
    const int lane = tid & 31;
    const int gid = lane >> 2;
    const int tig = lane & 3;
    const int r0 = q0 + wid * 16 + gid;

    const __half* Qf = g_qf + (size_t)bh * TT * HD;
    const __half* Kf = g_kf + (size_t)bh * TT * HD;
    const __half* Vf = g_vf + (size_t)bh * HD * TT;
    const __half* Vl = g_vl + (size_t)bh * HD * TT;

    const uint32_t laneB = (uint32_t)(((lane & 7) + ((lane >> 4) & 1) * 8) * AT_ROW
                                      + ((lane >> 3) & 1) * 16);

    // ---- Q fragments (fp16, single), direct ldg
    uint32_t qf[4][4];
#pragma unroll
    for (int ks = 0; ks < 4; ks++)
#pragma unroll
        for (int hv = 0; hv < 2; hv++)
#pragma unroll
            for (int rr = 0; rr < 2; rr++) {
                size_t o = (size_t)(r0 + rr * 8) * HD + ks * 16 + hv * 8 + tig * 2;
                qf[ks][hv * 2 + rr] = *(const uint32_t*)(Qf + o);
            }

    float oacc[8][4];
#pragma unroll
    for (int j = 0; j < 8; j++)
#pragma unroll
        for (int q = 0; q < 4; q++) oacc[j][q] = 0.f;
    float mr0 = -1e30f, mr1 = -1e30f, lr0 = 0.f, lr1 = 0.f;

    auto copyc = [&](int c, int bufi) {
        const int k0 = c * 64;
        uint32_t bbase = smb + bufi * AT_BUF;
#pragma unroll
        for (int l = 0; l < 6; l++) {
            const int tile = l >> 1;            // 0=Kf, 1=Vf, 2=Vl
            int e2 = (l & 1) * 256 + tid;       // 0..511
            int r = e2 >> 3;                    // 0..63
            int q = e2 & 7;                     // 0..7
            const void* src;
            if (tile == 0)      src = Kf + (size_t)(k0 + r) * HD + q * 8;
            else if (tile == 1) src = Vf + (size_t)r * TT + k0 + q * 8;
            else                src = Vl + (size_t)r * TT + k0 + q * 8;
            cpa16(bbase + tile * AT_TILE + r * AT_ROW + q * 16, src);
        }
    };

    const int jmax = (q0 >> 6) + 2;
    copyc(0, 0);
    CP_COMMIT();
    for (int c = 0; c < jmax; c++) {
        if (c + 1 < jmax) {
            copyc(c + 1, (c + 1) & 1);
            CP_COMMIT();
            CP_WAIT1();
        } else {
            CP_WAIT0();
        }
        __syncthreads();
        const uint32_t KT = smb + (uint32_t)(c & 1) * AT_BUF;
        const uint32_t VT = KT + AT_TILE;

        // ---- S = Q K^T, single fp16 product
        float s[8][4];
#pragma unroll
        for (int j = 0; j < 8; j++)
#pragma unroll
            for (int q = 0; q < 4; q++) s[j][q] = 0.f;
#pragma unroll
        for (int ks = 0; ks < 4; ks++) {
#pragma unroll
            for (int jp = 0; jp < 4; jp++) {
                uint32_t kaddr = KT + laneB + jp * 16 * AT_ROW + ks * 32;
                uint32_t rk[4];
                LDSM4(rk, kaddr);
#pragma unroll
                for (int t = 0; t < 2; t++) {
                    int j = 2 * jp + t;
                    mma16816h(s[j], qf[ks], rk[2 * t], rk[2 * t + 1]);
                }
            }
        }

        // scale into base-2 logit domain
        const int k0 = c * 64;
#pragma unroll
        for (int j = 0; j < 8; j++)
#pragma unroll
            for (int q = 0; q < 4; q++) s[j][q] *= SCL2;
        if (c >= jmax - 2) {
#pragma unroll
            for (int j = 0; j < 8; j++) {
                int col = k0 + 8 * j + 2 * tig;
                if (col > r0)          s[j][0] = -1e30f;
                if (col + 1 > r0)      s[j][1] = -1e30f;
                if (col > r0 + 8)      s[j][2] = -1e30f;
                if (col + 1 > r0 + 8)  s[j][3] = -1e30f;
            }
        }

        // ---- online softmax (base-2)
        float pm0 = -1e30f, pm1 = -1e30f;
#pragma unroll
        for (int j = 0; j < 8; j++) {
            pm0 = fmaxf(pm0, fmaxf(s[j][0], s[j][1]));
            pm1 = fmaxf(pm1, fmaxf(s[j][2], s[j][3]));
        }
        pm0 = fmaxf(pm0, __shfl_xor_sync(0xffffffffu, pm0, 1));
        pm0 = fmaxf(pm0, __shfl_xor_sync(0xffffffffu, pm0, 2));
        pm1 = fmaxf(pm1, __shfl_xor_sync(0xffffffffu, pm1, 1));
        pm1 = fmaxf(pm1, __shfl_xor_sync(0xffffffffu, pm1, 2));
        float mn0 = fmaxf(mr0, pm0), mn1 = fmaxf(mr1, pm1);
        float a0 = ex2f(mr0 - mn0), a1 = ex2f(mr1 - mn1);
        float sum0 = 0.f, sum1 = 0.f;
#pragma unroll
        for (int j = 0; j < 8; j++) {
            s[j][0] = ex2f(s[j][0] - mn0);
            s[j][1] = ex2f(s[j][1] - mn0);
            s[j][2] = ex2f(s[j][2] - mn1);
            s[j][3] = ex2f(s[j][3] - mn1);
            sum0 += s[j][0] + s[j][1];
            sum1 += s[j][2] + s[j][3];
        }
        sum0 += __shfl_xor_sync(0xffffffffu, sum0, 1);
        sum0 += __shfl_xor_sync(0xffffffffu, sum0, 2);
        sum1 += __shfl_xor_sync(0xffffffffu, sum1, 1);
        sum1 += __shfl_xor_sync(0xffffffffu, sum1, 2);
        lr0 = lr0 * a0 + sum0;
        lr1 = lr1 * a1 + sum1;
        mr0 = mn0; mr1 = mn1;
#pragma unroll
        for (int j = 0; j < 8; j++) {
            oacc[j][0] *= a0; oacc[j][1] *= a0;
            oacc[j][2] *= a1; oacc[j][3] *= a1;
        }

        // ---- O += P V (pf * vh + pf * vl), P single fp16, packed per-ks
#pragma unroll
        for (int ks = 0; ks < 4; ks++) {
            uint32_t pf[4];
            int j0 = 2 * ks, j1 = 2 * ks + 1;
#pragma unroll
            for (int part = 0; part < 4; part++) {
                int jj = (part < 2) ? j0 : j1;
                int qa = (part & 1) * 2;
                pf[part] = h2u(__floats2half2_rn(s[jj][qa], s[jj][qa + 1]));
            }
#pragma unroll
            for (int jp = 0; jp < 4; jp++) {
                uint32_t vaddr = VT + laneB + jp * 16 * AT_ROW + ks * 32;
                uint32_t rh[4], rl[4];
                LDSM4(rh, vaddr);
                LDSM4(rl, vaddr + AT_TILE);
#pragma unroll
                for (int t = 0; t < 2; t++) {
                    int j = 2 * jp + t;
                    mma16816h(oacc[j], pf, rh[2 * t], rh[2 * t + 1]);
                    mma16816h(oacc[j], pf, rl[2 * t], rl[2 * t + 1]);
                }
            }
        }
        __syncthreads();
    }

    // ---- epilogue: normalize, write g_af (fp16 single) [B,T,C]
    const int b = bh >> 4;
    const int h = bh & 15;
    float inv0 = 1.f / lr0, inv1 = 1.f / lr1;
#pragma unroll
    for (int j = 0; j < 8; j++) {
        int d = 8 * j + 2 * tig;
        size_t o0 = ((size_t)(b * TT + r0)) * CC + h * HD + d;
        size_t o1 = ((size_t)(b * TT + r0 + 8)) * CC + h * HD + d;
        *(uint32_t*)(g_af + o0) =
            h2u(__floats2half2_rn(oacc[j][0] * inv0, oacc[j][1] * inv0));
        *(uint32_t*)(g_af + o1) =
            h2u(__floats2half2_rn(oacc[j][2] * inv1, oacc[j][3] * inv1));
    }
}

// ---------------------------------------------------------------------------

extern "C" void kernel_launch(void* const* d_in, const int* in_sizes, int n_in,
                              void* d_out, int out_size) {
    const float* x      = (const float*)d_in[0];
    const float* w_qkv  = (const float*)d_in[1];
    const float* w_proj = (const float*)d_in[2];
    const float* b_proj = (const float*)d_in[3];
    float* out = (float*)d_out;

    __half *xf, *wqf, *wql, *wpf, *wpl, *af;
    cudaGetSymbolAddress((void**)&xf,  g_xf);
    cudaGetSymbolAddress((void**)&wqf, g_wqf);
    cudaGetSymbolAddress((void**)&wql, g_wql);
    cudaGetSymbolAddress((void**)&wpf, g_wpf);
    cudaGetSymbolAddress((void**)&wpl, g_wpl);
    cudaGetSymbolAddress((void**)&af,  g_af);

    cudaFuncSetAttribute(qkv_gemm, cudaFuncAttributeMaxDynamicSharedMemorySize, GSMEM);
    cudaFuncSetAttribute(proj_gemm, cudaFuncAttributeMaxDynamicSharedMemorySize, GSMEM);
    cudaFuncSetAttribute(attn_kernel, cudaFuncAttributeMaxDynamicSharedMemorySize, ATT_SMEM_BYTES);

    tofp16_kernel<<<2048, 256>>>(x, xf, MROWS * CC / 4);
    split_kernel_h<<<2048, 256>>>(w_qkv, wqf, wql, N_QKV * CC / 4);
    split_kernel_h<<<1024, 256>>>(w_proj, wpf, wpl, CC * CC / 4);

    qkv_gemm<<<dim3(N_QKV / 128, MROWS / 128), 256, GSMEM>>>(xf, wqf, wql);
    attn_kernel<<<dim3(TT / 128, BB * HH), 256, ATT_SMEM_BYTES>>>();
    proj_gemm<<<dim3(CC / 128, MROWS / 128), 256, GSMEM>>>(af, wpf, wpl, b_proj, out);
}